// round 1
// baseline (speedup 1.0000x reference)
#include <cuda_runtime.h>
#include <math.h>

#define Nn0 2000
#define Nn1 6000
#define Nn2 4000
#define CC  128

// ---------------- scratch (static __device__, no allocation) ----------------
__device__ float g_h0[Nn0 * CC];
__device__ float g_h1[Nn1 * CC];
__device__ float g_h2[Nn2 * CC];
__device__ float g_X0[Nn0 * 6  * CC];   //  6 slices of 128
__device__ float g_X1[Nn1 * 12 * CC];   // 12 slices (h1 duplicated once)
__device__ float g_X2[Nn2 * 8  * CC];   //  8 slices
__device__ float g_W0[6  * CC * CC];
__device__ float g_W1[12 * CC * CC];
__device__ float g_W2[8  * CC * CC];

// slice -> original einsum k index (-1 => zero weight)
__constant__ int c_maps[3][12] = {
    {0, 3, 1, 4, 2, 5, -1, -1, -1, -1, -1, -1},   // X0: [h0,p,L0h0,L0p,L0^2h0,L0^2p]
    {0, 5, -1, 8, 1, 6, 3, 9, 2, 7, 4, 10},       // X1: [h1,q,h1dup,r,L1d h1,L1d q,L1u h1,L1u r,L1d2 h1,L1d2 q,L1u2 h1,L1u2 r]
    {0, 5, 1, 6, 2, 7, 3, 4, -1, -1, -1, -1},     // X2: [h2,s,L2d h2,L2d s,L2d2 h2,L2d2 s,L2u h2,L2u2 h2]
};

// ---------------- GEMM: C[M,N] = op(A)[M,K] @ B[K,N] --------------------------
// Requires: N % 128 == 0, K % 16 == 0. M may be ragged.
// TRANSA=false: A is [M,K] row-major (lda = row stride)
// TRANSA=true : A is [K,M] row-major (lda = row stride), computes A^T @ B
template <bool TRANSA>
__global__ __launch_bounds__(256)
void gemm_kernel(int M, int N, int K,
                 const float* __restrict__ A, int lda,
                 const float* __restrict__ B, int ldb,
                 float* __restrict__ C, int ldc)
{
    constexpr int BM = 96, BN = 128, BK = 16;
    __shared__ float As[2][BK][BM + 1];  // [k][m]
    __shared__ float Bs[2][BK][BN];      // [k][n]

    const int m0 = blockIdx.x * BM;
    const int n0 = blockIdx.y * BN;
    const int tid = threadIdx.x;
    const int tx = tid & 15;   // col group: 8 cols each
    const int ty = tid >> 4;   // row group: 6 rows each

    float acc[6][8];
#pragma unroll
    for (int i = 0; i < 6; i++)
#pragma unroll
        for (int j = 0; j < 8; j++) acc[i][j] = 0.f;

    const int nk = K >> 4;

    // ---- tile loaders ----
    auto loadA = [&](int kt, int buf) {
        if (!TRANSA) {
#pragma unroll
            for (int p0 = 0; p0 < 3; p0++) {
                int p = tid + p0 * 256;          // 0..767 float2 slots
                int r = p >> 3;                  // m-row 0..95
                int c = (p & 7) * 2;             // k-col 0..14
                int gm = m0 + r;
                float2 v = make_float2(0.f, 0.f);
                if (gm < M) v = *(const float2*)&A[(size_t)gm * lda + kt + c];
                As[buf][c][r]     = v.x;
                As[buf][c + 1][r] = v.y;
            }
        } else {
#pragma unroll
            for (int p0 = 0; p0 < 6; p0++) {
                int p = tid + p0 * 256;          // 0..1535
                int r = p / 96;                  // k 0..15
                int c = p % 96;                  // m 0..95
                float v = 0.f;
                if (m0 + c < M) v = A[(size_t)(kt + r) * lda + m0 + c];
                As[buf][r][c] = v;
            }
        }
    };
    auto loadB = [&](int kt, int buf) {
#pragma unroll
        for (int q0 = 0; q0 < 2; q0++) {
            int q = tid + q0 * 256;
            int r = q >> 5;                      // k 0..15
            int c = (q & 31) * 4;                // n 0..124
            float4 v = *(const float4*)&B[(size_t)(kt + r) * ldb + n0 + c];
            *(float4*)&Bs[buf][r][c] = v;
        }
    };

    loadA(0, 0);
    loadB(0, 0);
    __syncthreads();

    for (int t = 0; t < nk; t++) {
        int cur = t & 1;
        if (t + 1 < nk) {
            loadA((t + 1) << 4, cur ^ 1);
            loadB((t + 1) << 4, cur ^ 1);
        }
#pragma unroll
        for (int kk = 0; kk < BK; kk++) {
            float a[6];
#pragma unroll
            for (int i = 0; i < 6; i++) a[i] = As[cur][kk][ty * 6 + i];
            float4 b0 = *(const float4*)&Bs[cur][kk][tx * 8];
            float4 b1 = *(const float4*)&Bs[cur][kk][tx * 8 + 4];
            float b[8] = {b0.x, b0.y, b0.z, b0.w, b1.x, b1.y, b1.z, b1.w};
#pragma unroll
            for (int i = 0; i < 6; i++)
#pragma unroll
                for (int j = 0; j < 8; j++) acc[i][j] += a[i] * b[j];
        }
        __syncthreads();
    }

#pragma unroll
    for (int i = 0; i < 6; i++) {
        int gm = m0 + ty * 6 + i;
        if (gm < M) {
            float* cp = &C[(size_t)gm * ldc + n0 + tx * 8];
            *(float4*)cp       = make_float4(acc[i][0], acc[i][1], acc[i][2], acc[i][3]);
            *(float4*)(cp + 4) = make_float4(acc[i][4], acc[i][5], acc[i][6], acc[i][7]);
        }
    }
}

// ---------------- small kernels ----------------

// y[n,o] = sum_i x[n,i] * W[o,i] + b[o]   (torch Linear), one block per row
__global__ void linear_kernel(const float* __restrict__ x, const float* __restrict__ W,
                              const float* __restrict__ b, float* __restrict__ y)
{
    __shared__ float xs[CC];
    int n = blockIdx.x, o = threadIdx.x;
    xs[o] = x[(size_t)n * CC + o];
    __syncthreads();
    float acc = b[o];
    const float* wr = &W[(size_t)o * CC];
#pragma unroll 8
    for (int i = 0; i < CC; i++) acc += xs[i] * wr[i];
    y[(size_t)n * CC + o] = acc;
}

// copy [N,128] (ld 128) into dst with row stride ldd at column offset already folded in
__global__ void copy_rows_kernel(const float* __restrict__ src, float* __restrict__ dst,
                                 int N, int ldd)
{
    int n = blockIdx.x, t = threadIdx.x;
    if (n < N) dst[(size_t)n * ldd + t] = src[(size_t)n * CC + t];
}

// Wt[(s*128+i), o] = w[i,o,map[s]]  (or 0)
__global__ void build_wt_kernel(const float* __restrict__ w, float* __restrict__ Wt,
                                int which, int korig)
{
    int bi = blockIdx.x;
    int s = bi >> 7;
    int i = bi & 127;
    int o = threadIdx.x;
    int k = c_maps[which][s];
    float v = (k >= 0) ? w[((size_t)i * CC + o) * korig + k] : 0.f;
    Wt[((size_t)(s * CC + i)) * CC + o] = v;
}

// out[n,c] = sigmoid(dot(h0[n,:], out_w[c,:]) + out_b[c])
__global__ void head_kernel(const float* __restrict__ h0, const float* __restrict__ ow,
                            const float* __restrict__ ob, float* __restrict__ out, int total)
{
    int idx = blockIdx.x * blockDim.x + threadIdx.x;
    if (idx >= total) return;
    int n = idx >> 1, c = idx & 1;
    float acc = ob[c];
    const float* hr = &h0[(size_t)n * CC];
    const float* wr = &ow[(size_t)c * CC];
#pragma unroll 8
    for (int i = 0; i < CC; i++) acc += hr[i] * wr[i];
    out[idx] = 1.f / (1.f + expf(-acc));
}

// ---------------- host orchestration ----------------
static void gemm(bool ta, int M, int N, int K,
                 const float* A, int lda, const float* B, int ldb, float* Cm, int ldc)
{
    dim3 grid((M + 95) / 96, N / 128);
    if (ta) gemm_kernel<true ><<<grid, 256>>>(M, N, K, A, lda, B, ldb, Cm, ldc);
    else    gemm_kernel<false><<<grid, 256>>>(M, N, K, A, lda, B, ldb, Cm, ldc);
}

extern "C" void kernel_launch(void* const* d_in, const int* in_sizes, int n_in,
                              void* d_out, int out_size)
{
    (void)in_sizes; (void)n_in; (void)out_size;
    const float* x0    = (const float*)d_in[0];
    const float* x1    = (const float*)d_in[1];
    const float* x2    = (const float*)d_in[2];
    const float* L0    = (const float*)d_in[3];
    const float* L1d   = (const float*)d_in[4];
    const float* L1u   = (const float*)d_in[5];
    const float* L2d   = (const float*)d_in[6];
    const float* L2u   = (const float*)d_in[7];
    const float* B1    = (const float*)d_in[8];
    const float* B2    = (const float*)d_in[9];
    const float* in_w0 = (const float*)d_in[10];
    const float* in_b0 = (const float*)d_in[11];
    const float* in_w1 = (const float*)d_in[12];
    const float* in_b1 = (const float*)d_in[13];
    const float* in_w2 = (const float*)d_in[14];
    const float* in_b2 = (const float*)d_in[15];
    const float* lw[2][3] = {
        {(const float*)d_in[16], (const float*)d_in[17], (const float*)d_in[18]},
        {(const float*)d_in[19], (const float*)d_in[20], (const float*)d_in[21]},
    };
    const float* out_w = (const float*)d_in[22];
    const float* out_b = (const float*)d_in[23];
    float* out = (float*)d_out;

    void* p;
    cudaGetSymbolAddress(&p, g_h0); float* h0 = (float*)p;
    cudaGetSymbolAddress(&p, g_h1); float* h1 = (float*)p;
    cudaGetSymbolAddress(&p, g_h2); float* h2 = (float*)p;
    cudaGetSymbolAddress(&p, g_X0); float* X0 = (float*)p;
    cudaGetSymbolAddress(&p, g_X1); float* X1 = (float*)p;
    cudaGetSymbolAddress(&p, g_X2); float* X2 = (float*)p;
    cudaGetSymbolAddress(&p, g_W0); float* W0 = (float*)p;
    cudaGetSymbolAddress(&p, g_W1); float* W1 = (float*)p;
    cudaGetSymbolAddress(&p, g_W2); float* W2 = (float*)p;

    const int LD0 = 6 * CC, LD1 = 12 * CC, LD2 = 8 * CC;

    // input linears
    linear_kernel<<<Nn0, CC>>>(x0, in_w0, in_b0, h0);
    linear_kernel<<<Nn1, CC>>>(x1, in_w1, in_b1, h1);
    linear_kernel<<<Nn2, CC>>>(x2, in_w2, in_b2, h2);

    for (int layer = 0; layer < 2; layer++) {
        // permuted/flattened einsum weights
        build_wt_kernel<<<6 * CC,  CC>>>(lw[layer][0], W0, 0, 6);
        build_wt_kernel<<<12 * CC, CC>>>(lw[layer][1], W1, 1, 11);
        build_wt_kernel<<<8 * CC,  CC>>>(lw[layer][2], W2, 2, 8);

        // ---- node space: X0 = [h0, p, L0*{h0,p}, L0^2*{h0,p}] ----
        copy_rows_kernel<<<Nn0, CC>>>(h0, X0 + 0, Nn0, LD0);
        gemm(false, Nn0, 128, Nn1, B1, Nn1, h1, CC, X0 + 128, LD0);          // p = B1 @ h1
        gemm(false, Nn0, 256, Nn0, L0, Nn0, X0 + 0,   LD0, X0 + 256, LD0);   // L0 @ [h0,p]
        gemm(false, Nn0, 256, Nn0, L0, Nn0, X0 + 256, LD0, X0 + 512, LD0);   // L0^2

        // ---- edge space: X1 = [h1, q, h1, r, L1d*{h1,q}, L1u*{h1,r}, ...] ----
        copy_rows_kernel<<<Nn1, CC>>>(h1, X1 + 0,   Nn1, LD1);
        copy_rows_kernel<<<Nn1, CC>>>(h1, X1 + 256, Nn1, LD1);
        gemm(true,  Nn1, 128, Nn0, B1, Nn1, h0, CC, X1 + 128, LD1);          // q = B1^T @ h0
        gemm(false, Nn1, 128, Nn2, B2, Nn2, h2, CC, X1 + 384, LD1);          // r = B2 @ h2
        gemm(false, Nn1, 256, Nn1, L1d, Nn1, X1 + 0,    LD1, X1 + 512,  LD1);
        gemm(false, Nn1, 256, Nn1, L1u, Nn1, X1 + 256,  LD1, X1 + 768,  LD1);
        gemm(false, Nn1, 256, Nn1, L1d, Nn1, X1 + 512,  LD1, X1 + 1024, LD1);
        gemm(false, Nn1, 256, Nn1, L1u, Nn1, X1 + 768,  LD1, X1 + 1280, LD1);

        // ---- face space: X2 = [h2, s, L2d*{h2,s}, L2d^2*{h2,s}, L2u h2, L2u^2 h2] ----
        copy_rows_kernel<<<Nn2, CC>>>(h2, X2 + 0, Nn2, LD2);
        gemm(true,  Nn2, 128, Nn1, B2, Nn2, h1, CC, X2 + 128, LD2);          // s = B2^T @ h1
        gemm(false, Nn2, 256, Nn2, L2d, Nn2, X2 + 0,   LD2, X2 + 256, LD2);
        gemm(false, Nn2, 256, Nn2, L2d, Nn2, X2 + 256, LD2, X2 + 512, LD2);
        gemm(false, Nn2, 128, Nn2, L2u, Nn2, X2 + 0,   LD2, X2 + 768, LD2);
        gemm(false, Nn2, 128, Nn2, L2u, Nn2, X2 + 768, LD2, X2 + 896, LD2);

        // ---- einsums: h' = X @ Wt ----
        gemm(false, Nn0, 128, 6 * CC,  X0, LD0, W0, CC, h0, CC);
        gemm(false, Nn1, 128, 12 * CC, X1, LD1, W1, CC, h1, CC);
        gemm(false, Nn2, 128, 8 * CC,  X2, LD2, W2, CC, h2, CC);
    }

    head_kernel<<<(Nn0 * 2 + 255) / 256, 256>>>(h0, out_w, out_b, out, Nn0 * 2);
}

// round 4
// speedup vs baseline: 2.4887x; 2.4887x over previous
#include <cuda_runtime.h>
#include <cuda_bf16.h>
#include <math.h>
#include <stdint.h>

#define Nn0 2000
#define Nn1 6000
#define Nn2 4000
#define CC  128

// ================= static scratch (no allocation) =================
__device__ float g_h0[Nn0 * CC];
__device__ float g_h1[Nn1 * CC];
__device__ float g_h2[Nn2 * CC];
__device__ float g_X0f[Nn0 * 6  * CC];
__device__ float g_X1f[Nn1 * 12 * CC];
__device__ float g_X2f[Nn2 * 8  * CC];

// bf16 hi/lo splits of operators (built once per call)
__device__ __nv_bfloat16 g_L0h[Nn0 * Nn0],  g_L0l[Nn0 * Nn0];
__device__ __nv_bfloat16 g_L1dh[Nn1 * Nn1], g_L1dl[Nn1 * Nn1];
__device__ __nv_bfloat16 g_L1uh[Nn1 * Nn1], g_L1ul[Nn1 * Nn1];
__device__ __nv_bfloat16 g_L2dh[Nn2 * Nn2], g_L2dl[Nn2 * Nn2];
__device__ __nv_bfloat16 g_L2uh[Nn2 * Nn2], g_L2ul[Nn2 * Nn2];
__device__ __nv_bfloat16 g_B1h[Nn0 * Nn1],  g_B1l[Nn0 * Nn1];
__device__ __nv_bfloat16 g_B1th[Nn1 * Nn0], g_B1tl[Nn1 * Nn0];
__device__ __nv_bfloat16 g_B2h[Nn1 * Nn2],  g_B2l[Nn1 * Nn2];
__device__ __nv_bfloat16 g_B2th[Nn2 * Nn1], g_B2tl[Nn2 * Nn1];

// bf16 splits of X (einsum A operands)
__device__ __nv_bfloat16 g_X0h[Nn0 * 6 * CC],  g_X0l[Nn0 * 6 * CC];
__device__ __nv_bfloat16 g_X1h[Nn1 * 12 * CC], g_X1l[Nn1 * 12 * CC];
__device__ __nv_bfloat16 g_X2h[Nn2 * 8 * CC],  g_X2l[Nn2 * 8 * CC];

// transposed bf16 B-operand buffers
__device__ __nv_bfloat16 g_btCh[256 * Nn1], g_btCl[256 * Nn1];
__device__ __nv_bfloat16 g_bth0h[CC * Nn0], g_bth0l[CC * Nn0];
__device__ __nv_bfloat16 g_bth1h[CC * Nn1], g_bth1l[CC * Nn1];
__device__ __nv_bfloat16 g_bth2h[CC * Nn2], g_bth2l[CC * Nn2];

// einsum weights, transposed [128, S*128] bf16 hi/lo
__device__ __nv_bfloat16 g_W0h[CC * 6 * CC],  g_W0l[CC * 6 * CC];
__device__ __nv_bfloat16 g_W1h[CC * 12 * CC], g_W1l[CC * 12 * CC];
__device__ __nv_bfloat16 g_W2h[CC * 8 * CC],  g_W2l[CC * 8 * CC];

__constant__ int c_maps[3][12] = {
    {0, 3, 1, 4, 2, 5, -1, -1, -1, -1, -1, -1},
    {0, 5, -1, 8, 1, 6, 3, 9, 2, 7, 4, 10},
    {0, 5, 1, 6, 2, 7, 3, 4, -1, -1, -1, -1},
};

// ================= PTX helpers (all plain sm_80+ PTX, no arch suffix) =======
__device__ __forceinline__ uint32_t smem_u32(const void* p) {
    uint32_t a;
    asm("{ .reg .u64 t; cvta.to.shared.u64 t, %1; cvt.u32.u64 %0, t; }" : "=r"(a) : "l"(p));
    return a;
}
__device__ __forceinline__ void ldsm_x4(uint32_t* r, uint32_t a) {
    asm volatile("ldmatrix.sync.aligned.m8n8.x4.shared.b16 {%0,%1,%2,%3}, [%4];"
                 : "=r"(r[0]), "=r"(r[1]), "=r"(r[2]), "=r"(r[3]) : "r"(a));
}
__device__ __forceinline__ void mma_bf16(float* c, const uint32_t* a, const uint32_t* b) {
    asm volatile(
        "mma.sync.aligned.m16n8k16.row.col.f32.bf16.bf16.f32 "
        "{%0,%1,%2,%3}, {%4,%5,%6,%7}, {%8,%9}, {%0,%1,%2,%3};"
        : "+f"(c[0]), "+f"(c[1]), "+f"(c[2]), "+f"(c[3])
        : "r"(a[0]), "r"(a[1]), "r"(a[2]), "r"(a[3]), "r"(b[0]), "r"(b[1]));
}
__device__ __forceinline__ void cp_async16(uint32_t dst, const void* src, int sz) {
    asm volatile("cp.async.cg.shared.global [%0], [%1], 16, %2;"
                 :: "r"(dst), "l"(src), "r"(sz));
}
// swizzled byte addr within a [128 rows x 32 bf16] tile (64B rows, 16B chunks)
__device__ __forceinline__ uint32_t sw_addr(uint32_t tile_base, int r, int chunk) {
    return tile_base + (uint32_t)(r * 64) + (uint32_t)((chunk ^ ((r >> 1) & 3)) << 4);
}

// ================= bf16x3 HMMA GEMM ==========================================
// C[M, Nall] = (Ah+Al)[M,K] @ (Bh+Bl)^T,  B operands stored [Nall, K] K-major.
// CTA tile 128x128, BK=32, 4-stage cp.async pipeline.
#define MM_SMEM (4 * 4 * 8192)

__global__ __launch_bounds__(256)
void mm_kernel(int M, int K,
               const __nv_bfloat16* __restrict__ Ah, const __nv_bfloat16* __restrict__ Al, int lda,
               const __nv_bfloat16* __restrict__ Bh, const __nv_bfloat16* __restrict__ Bl, int ldb,
               float* __restrict__ C, int ldc)
{
    extern __shared__ __align__(128) char smem[];
    const uint32_t sbase = smem_u32(smem);
    const int tid = threadIdx.x, lane = tid & 31, wid = tid >> 5;
    const int wm = wid & 1, wn = wid >> 1;            // warp grid 2 x 4
    const int m0 = blockIdx.x * 128, n0 = blockIdx.y * 128;
    const int mrows = (M - m0 < 128) ? (M - m0) : 128;
    Ah += (size_t)m0 * lda;  Al += (size_t)m0 * lda;
    Bh += (size_t)n0 * ldb;  Bl += (size_t)n0 * ldb;
    const int nk = (K + 31) >> 5;

    float acc[4][4][4];
#pragma unroll
    for (int i = 0; i < 4; i++)
#pragma unroll
        for (int j = 0; j < 4; j++)
#pragma unroll
            for (int v = 0; v < 4; v++) acc[i][j][v] = 0.f;

    // ---- stage loader: tiles Ah|Al|Bh|Bl, each 128 x 32 bf16 ----
    auto load_stage = [&](int t) {
        const uint32_t sb = sbase + (uint32_t)(t & 3) * 32768;
        const int k0 = t << 5;
#pragma unroll
        for (int i = 0; i < 8; i++) {
            int idx = tid + i * 256;
            int tile = idx >> 9;
            int rem  = idx & 511;
            int r = rem >> 2, c = rem & 3;
            const __nv_bfloat16* gp;
            int ok;
            if (tile < 2) {
                gp = (tile == 0 ? Ah : Al) + (size_t)r * lda + k0 + c * 8;
                ok = (r < mrows) && (k0 + c * 8 < K);
            } else {
                gp = (tile == 2 ? Bh : Bl) + (size_t)r * ldb + k0 + c * 8;
                ok = (k0 + c * 8 < K);
            }
            cp_async16(sb + (uint32_t)tile * 8192 + sw_addr(0, r, c), gp, ok ? 16 : 0);
        }
    };

    // prologue: 3 stages in flight
#pragma unroll
    for (int s = 0; s < 3; s++) {
        if (s < nk) load_stage(s);
        asm volatile("cp.async.commit_group;" ::: "memory");
    }

    const int frag_r = lane & 15;        // row within 16-row group (A: m, B: n)
    const int frag_c = lane >> 4;        // k8 half selector

    for (int t = 0; t < nk; t++) {
        asm volatile("cp.async.wait_group 2;" ::: "memory");
        __syncthreads();
        const uint32_t sb = sbase + (uint32_t)(t & 3) * 32768;
        const uint32_t tAh = sb, tAl = sb + 8192, tBh = sb + 16384, tBl = sb + 24576;

#pragma unroll
        for (int ks = 0; ks < 2; ks++) {
            const int ch = ks * 2 + frag_c;
            uint32_t ah[4][4], al[4][4], bh[4][2], bl[4][2];
#pragma unroll
            for (int mt = 0; mt < 4; mt++) {
                int r = wm * 64 + mt * 16 + frag_r;
                ldsm_x4(ah[mt], sw_addr(tAh, r, ch));
                ldsm_x4(al[mt], sw_addr(tAl, r, ch));
            }
#pragma unroll
            for (int j = 0; j < 2; j++) {
                int r = wn * 32 + j * 16 + frag_r;
                uint32_t rr[4];
                // B stored [N,K] K-major == col-major of (k,n): same frag load as A.
                // rr[0]=b0(n sub 0), rr[1]=b0(n sub 1), rr[2]=b1(sub 0), rr[3]=b1(sub 1)
                ldsm_x4(rr, sw_addr(tBh, r, ch));
                bh[2 * j][0] = rr[0]; bh[2 * j][1] = rr[2];
                bh[2 * j + 1][0] = rr[1]; bh[2 * j + 1][1] = rr[3];
                ldsm_x4(rr, sw_addr(tBl, r, ch));
                bl[2 * j][0] = rr[0]; bl[2 * j][1] = rr[2];
                bl[2 * j + 1][0] = rr[1]; bl[2 * j + 1][1] = rr[3];
            }
#pragma unroll
            for (int mt = 0; mt < 4; mt++)
#pragma unroll
                for (int nt = 0; nt < 4; nt++) {
                    mma_bf16(acc[mt][nt], ah[mt], bh[nt]);
                    mma_bf16(acc[mt][nt], ah[mt], bl[nt]);
                    mma_bf16(acc[mt][nt], al[mt], bh[nt]);
                }
        }
        if (t + 3 < nk) load_stage(t + 3);
        asm volatile("cp.async.commit_group;" ::: "memory");
    }

    // ---- epilogue: fp32 STG ----
    const int er = lane >> 2, ec = (lane & 3) * 2;
#pragma unroll
    for (int mt = 0; mt < 4; mt++) {
        int row0 = m0 + wm * 64 + mt * 16 + er;
#pragma unroll
        for (int nt = 0; nt < 4; nt++) {
            int col = n0 + wn * 32 + nt * 8 + ec;
            if (row0 < M)
                *(float2*)&C[(size_t)row0 * ldc + col] = make_float2(acc[mt][nt][0], acc[mt][nt][1]);
            if (row0 + 8 < M)
                *(float2*)&C[(size_t)(row0 + 8) * ldc + col] = make_float2(acc[mt][nt][2], acc[mt][nt][3]);
        }
    }
}

// ================= conversion kernels =================
__global__ void splitA_kernel(const float* __restrict__ src,
                              __nv_bfloat16* __restrict__ dh, __nv_bfloat16* __restrict__ dl,
                              size_t total)
{
    size_t i = (size_t)blockIdx.x * blockDim.x + threadIdx.x;
    if (i >= total) return;
    float v = src[i];
    __nv_bfloat16 h = __float2bfloat16(v);
    dh[i] = h;
    dl[i] = __float2bfloat16(v - __bfloat162float(h));
}

// dst[n*Kd + k] = src[k*lds + n]
__global__ void splitBt_kernel(const float* __restrict__ src, int lds, int Kd, int Nd,
                               __nv_bfloat16* __restrict__ dh, __nv_bfloat16* __restrict__ dl)
{
    __shared__ float tile[32][33];
    int k0 = blockIdx.x * 32, n0 = blockIdx.y * 32;
    int tx = threadIdx.x, ty = threadIdx.y;
    for (int i = ty; i < 32; i += 8) {
        int k = k0 + i, n = n0 + tx;
        tile[i][tx] = (k < Kd && n < Nd) ? src[(size_t)k * lds + n] : 0.f;
    }
    __syncthreads();
    for (int i = ty; i < 32; i += 8) {
        int n = n0 + i, k = k0 + tx;
        if (n < Nd && k < Kd) {
            float v = tile[tx][i];
            __nv_bfloat16 h = __float2bfloat16(v);
            dh[(size_t)n * Kd + k] = h;
            dl[(size_t)n * Kd + k] = __float2bfloat16(v - __bfloat162float(h));
        }
    }
}

__global__ void build_wt_kernel(const float* __restrict__ w,
                                __nv_bfloat16* __restrict__ dh, __nv_bfloat16* __restrict__ dl,
                                int which, int korig, int S)
{
    int bi = blockIdx.x;
    int s = bi >> 7, o = bi & 127;
    int i = threadIdx.x;
    int k = c_maps[which][s];
    float v = (k >= 0) ? w[((size_t)i * CC + o) * korig + k] : 0.f;
    __nv_bfloat16 h = __float2bfloat16(v);
    size_t idx = (size_t)o * (S * CC) + s * CC + i;
    dh[idx] = h;
    dl[idx] = __float2bfloat16(v - __bfloat162float(h));
}

// ================= small fp32 kernels =================
__global__ void linear_kernel(const float* __restrict__ x, const float* __restrict__ W,
                              const float* __restrict__ b, float* __restrict__ y)
{
    __shared__ float xs[CC];
    int n = blockIdx.x, o = threadIdx.x;
    xs[o] = x[(size_t)n * CC + o];
    __syncthreads();
    float acc = b[o];
    const float* wr = &W[(size_t)o * CC];
#pragma unroll 8
    for (int i = 0; i < CC; i++) acc += xs[i] * wr[i];
    y[(size_t)n * CC + o] = acc;
}

__global__ void copy_rows_kernel(const float* __restrict__ src, float* __restrict__ dst,
                                 int N, int ldd)
{
    int n = blockIdx.x, t = threadIdx.x;
    if (n < N) dst[(size_t)n * ldd + t] = src[(size_t)n * CC + t];
}

__global__ void head_kernel(const float* __restrict__ h0, const float* __restrict__ ow,
                            const float* __restrict__ ob, float* __restrict__ out, int total)
{
    int idx = blockIdx.x * blockDim.x + threadIdx.x;
    if (idx >= total) return;
    int n = idx >> 1, c = idx & 1;
    float acc = ob[c];
    const float* hr = &h0[(size_t)n * CC];
    const float* wr = &ow[(size_t)c * CC];
#pragma unroll 8
    for (int i = 0; i < CC; i++) acc += hr[i] * wr[i];
    out[idx] = 1.f / (1.f + expf(-acc));
}

// ================= host orchestration =================
static void mm(const __nv_bfloat16* Ah, const __nv_bfloat16* Al, int lda,
               const __nv_bfloat16* Bh, const __nv_bfloat16* Bl, int ldb,
               float* C, int ldc, int M, int N, int K)
{
    dim3 g((M + 127) / 128, N / 128);
    mm_kernel<<<g, 256, MM_SMEM>>>(M, K, Ah, Al, lda, Bh, Bl, ldb, C, ldc);
}

static void splitA(const float* src, __nv_bfloat16* dh, __nv_bfloat16* dl, size_t total)
{
    splitA_kernel<<<(unsigned)((total + 255) / 256), 256>>>(src, dh, dl, total);
}

static void splitBt(const float* src, int lds, int Kd, int Nd,
                    __nv_bfloat16* dh, __nv_bfloat16* dl)
{
    dim3 g((Kd + 31) / 32, (Nd + 31) / 32);
    splitBt_kernel<<<g, dim3(32, 8)>>>(src, lds, Kd, Nd, dh, dl);
}

#define SYM(v, g) { void* p_; cudaGetSymbolAddress(&p_, g); v = (decltype(v))p_; }

extern "C" void kernel_launch(void* const* d_in, const int* in_sizes, int n_in,
                              void* d_out, int out_size)
{
    (void)in_sizes; (void)n_in; (void)out_size;
    const float* x0    = (const float*)d_in[0];
    const float* x1    = (const float*)d_in[1];
    const float* x2    = (const float*)d_in[2];
    const float* L0    = (const float*)d_in[3];
    const float* L1d   = (const float*)d_in[4];
    const float* L1u   = (const float*)d_in[5];
    const float* L2d   = (const float*)d_in[6];
    const float* L2u   = (const float*)d_in[7];
    const float* B1    = (const float*)d_in[8];
    const float* B2    = (const float*)d_in[9];
    const float* in_w0 = (const float*)d_in[10];
    const float* in_b0 = (const float*)d_in[11];
    const float* in_w1 = (const float*)d_in[12];
    const float* in_b1 = (const float*)d_in[13];
    const float* in_w2 = (const float*)d_in[14];
    const float* in_b2 = (const float*)d_in[15];
    const float* lw[2][3] = {
        {(const float*)d_in[16], (const float*)d_in[17], (const float*)d_in[18]},
        {(const float*)d_in[19], (const float*)d_in[20], (const float*)d_in[21]},
    };
    const float* out_w = (const float*)d_in[22];
    const float* out_b = (const float*)d_in[23];
    float* out = (float*)d_out;

    cudaFuncSetAttribute(mm_kernel, cudaFuncAttributeMaxDynamicSharedMemorySize, MM_SMEM);

    float *h0, *h1, *h2, *X0f, *X1f, *X2f;
    SYM(h0, g_h0); SYM(h1, g_h1); SYM(h2, g_h2);
    SYM(X0f, g_X0f); SYM(X1f, g_X1f); SYM(X2f, g_X2f);
    __nv_bfloat16 *L0h, *L0l, *L1dh, *L1dl, *L1uh, *L1ul, *L2dh, *L2dl, *L2uh, *L2ul;
    __nv_bfloat16 *B1h, *B1l, *B1th, *B1tl, *B2h, *B2l, *B2th, *B2tl;
    SYM(L0h, g_L0h); SYM(L0l, g_L0l);
    SYM(L1dh, g_L1dh); SYM(L1dl, g_L1dl); SYM(L1uh, g_L1uh); SYM(L1ul, g_L1ul);
    SYM(L2dh, g_L2dh); SYM(L2dl, g_L2dl); SYM(L2uh, g_L2uh); SYM(L2ul, g_L2ul);
    SYM(B1h, g_B1h); SYM(B1l, g_B1l); SYM(B1th, g_B1th); SYM(B1tl, g_B1tl);
    SYM(B2h, g_B2h); SYM(B2l, g_B2l); SYM(B2th, g_B2th); SYM(B2tl, g_B2tl);
    __nv_bfloat16 *X0h, *X0l, *X1h, *X1l, *X2h, *X2l;
    SYM(X0h, g_X0h); SYM(X0l, g_X0l); SYM(X1h, g_X1h); SYM(X1l, g_X1l);
    SYM(X2h, g_X2h); SYM(X2l, g_X2l);
    __nv_bfloat16 *btCh, *btCl, *bh0h, *bh0l, *bh1h, *bh1l, *bh2h, *bh2l;
    SYM(btCh, g_btCh); SYM(btCl, g_btCl);
    SYM(bh0h, g_bth0h); SYM(bh0l, g_bth0l);
    SYM(bh1h, g_bth1h); SYM(bh1l, g_bth1l);
    SYM(bh2h, g_bth2h); SYM(bh2l, g_bth2l);
    __nv_bfloat16 *W0h, *W0l, *W1h, *W1l, *W2h, *W2l;
    SYM(W0h, g_W0h); SYM(W0l, g_W0l); SYM(W1h, g_W1h); SYM(W1l, g_W1l);
    SYM(W2h, g_W2h); SYM(W2l, g_W2l);

    const int LD0 = 6 * CC, LD1 = 12 * CC, LD2 = 8 * CC;

    // ---- operator conversions ----
    splitA(L0,  L0h,  L0l,  (size_t)Nn0 * Nn0);
    splitA(L1d, L1dh, L1dl, (size_t)Nn1 * Nn1);
    splitA(L1u, L1uh, L1ul, (size_t)Nn1 * Nn1);
    splitA(L2d, L2dh, L2dl, (size_t)Nn2 * Nn2);
    splitA(L2u, L2uh, L2ul, (size_t)Nn2 * Nn2);
    splitA(B1,  B1h,  B1l,  (size_t)Nn0 * Nn1);
    splitA(B2,  B2h,  B2l,  (size_t)Nn1 * Nn2);
    splitBt(B1, Nn1, Nn0, Nn1, B1th, B1tl);
    splitBt(B2, Nn2, Nn1, Nn2, B2th, B2tl);

    // ---- input linears ----
    linear_kernel<<<Nn0, CC>>>(x0, in_w0, in_b0, h0);
    linear_kernel<<<Nn1, CC>>>(x1, in_w1, in_b1, h1);
    linear_kernel<<<Nn2, CC>>>(x2, in_w2, in_b2, h2);

    for (int layer = 0; layer < 2; layer++) {
        build_wt_kernel<<<6 * CC,  CC>>>(lw[layer][0], W0h, W0l, 0, 6,  6);
        build_wt_kernel<<<12 * CC, CC>>>(lw[layer][1], W1h, W1l, 1, 11, 12);
        build_wt_kernel<<<8 * CC,  CC>>>(lw[layer][2], W2h, W2l, 2, 8,  8);

        splitBt(h0, CC, Nn0, CC, bh0h, bh0l);
        splitBt(h1, CC, Nn1, CC, bh1h, bh1l);
        splitBt(h2, CC, Nn2, CC, bh2h, bh2l);

        copy_rows_kernel<<<Nn0, CC>>>(h0, X0f + 0, Nn0, LD0);
        copy_rows_kernel<<<Nn1, CC>>>(h1, X1f + 0, Nn1, LD1);
        copy_rows_kernel<<<Nn1, CC>>>(h1, X1f + 256, Nn1, LD1);
        copy_rows_kernel<<<Nn2, CC>>>(h2, X2f + 0, Nn2, LD2);
        mm(B1h,  B1l,  Nn1, bh1h, bh1l, Nn1, X0f + 128, LD0, Nn0, 128, Nn1);   // p = B1 @ h1
        mm(B1th, B1tl, Nn0, bh0h, bh0l, Nn0, X1f + 128, LD1, Nn1, 128, Nn0);   // q = B1^T @ h0
        mm(B2h,  B2l,  Nn2, bh2h, bh2l, Nn2, X1f + 384, LD1, Nn1, 128, Nn2);   // r = B2 @ h2
        mm(B2th, B2tl, Nn1, bh1h, bh1l, Nn1, X2f + 128, LD2, Nn2, 128, Nn1);   // s = B2^T @ h1

        // node chains
        splitBt(X0f + 0,   LD0, Nn0, 256, btCh, btCl);
        mm(L0h, L0l, Nn0, btCh, btCl, Nn0, X0f + 256, LD0, Nn0, 256, Nn0);
        splitBt(X0f + 256, LD0, Nn0, 256, btCh, btCl);
        mm(L0h, L0l, Nn0, btCh, btCl, Nn0, X0f + 512, LD0, Nn0, 256, Nn0);

        // edge chains
        splitBt(X1f + 0,   LD1, Nn1, 256, btCh, btCl);
        mm(L1dh, L1dl, Nn1, btCh, btCl, Nn1, X1f + 512,  LD1, Nn1, 256, Nn1);
        splitBt(X1f + 256, LD1, Nn1, 256, btCh, btCl);
        mm(L1uh, L1ul, Nn1, btCh, btCl, Nn1, X1f + 768,  LD1, Nn1, 256, Nn1);
        splitBt(X1f + 512, LD1, Nn1, 256, btCh, btCl);
        mm(L1dh, L1dl, Nn1, btCh, btCl, Nn1, X1f + 1024, LD1, Nn1, 256, Nn1);
        splitBt(X1f + 768, LD1, Nn1, 256, btCh, btCl);
        mm(L1uh, L1ul, Nn1, btCh, btCl, Nn1, X1f + 1280, LD1, Nn1, 256, Nn1);

        // face chains
        splitBt(X2f + 0,   LD2, Nn2, 256, btCh, btCl);
        mm(L2dh, L2dl, Nn2, btCh, btCl, Nn2, X2f + 256, LD2, Nn2, 256, Nn2);
        splitBt(X2f + 256, LD2, Nn2, 256, btCh, btCl);
        mm(L2dh, L2dl, Nn2, btCh, btCl, Nn2, X2f + 512, LD2, Nn2, 256, Nn2);
        mm(L2uh, L2ul, Nn2, bh2h, bh2l, Nn2, X2f + 768, LD2, Nn2, 128, Nn2);
        splitBt(X2f + 768, LD2, Nn2, 128, btCh, btCl);
        mm(L2uh, L2ul, Nn2, btCh, btCl, Nn2, X2f + 896, LD2, Nn2, 128, Nn2);

        // einsums
        splitA(X0f, X0h, X0l, (size_t)Nn0 * LD0);
        splitA(X1f, X1h, X1l, (size_t)Nn1 * LD1);
        splitA(X2f, X2h, X2l, (size_t)Nn2 * LD2);
        mm(X0h, X0l, LD0, W0h, W0l, LD0, h0, CC, Nn0, 128, LD0);
        mm(X1h, X1l, LD1, W1h, W1l, LD1, h1, CC, Nn1, 128, LD1);
        mm(X2h, X2l, LD2, W2h, W2l, LD2, h2, CC, Nn2, 128, LD2);
    }

    head_kernel<<<(Nn0 * 2 + 255) / 256, 256>>>(h0, out_w, out_b, out, Nn0 * 2);
}

// round 5
// speedup vs baseline: 4.6952x; 1.8866x over previous
#include <cuda_runtime.h>
#include <cuda_bf16.h>
#include <math.h>
#include <stdint.h>

#define Nn0 2000
#define Nn1 6000
#define Nn2 4000
#define CC  128

// ================= static scratch (no allocation) =================
__device__ float g_h0[Nn0 * CC];
__device__ float g_h1[Nn1 * CC];
__device__ float g_h2[Nn2 * CC];
__device__ float g_X0f[Nn0 * 6  * CC];
__device__ float g_X1f[Nn1 * 12 * CC];
__device__ float g_X2f[Nn2 * 8  * CC];

__device__ __nv_bfloat16 g_L0h[Nn0 * Nn0],  g_L0l[Nn0 * Nn0];
__device__ __nv_bfloat16 g_L1dh[Nn1 * Nn1], g_L1dl[Nn1 * Nn1];
__device__ __nv_bfloat16 g_L1uh[Nn1 * Nn1], g_L1ul[Nn1 * Nn1];
__device__ __nv_bfloat16 g_L2dh[Nn2 * Nn2], g_L2dl[Nn2 * Nn2];
__device__ __nv_bfloat16 g_L2uh[Nn2 * Nn2], g_L2ul[Nn2 * Nn2];
__device__ __nv_bfloat16 g_B1h[Nn0 * Nn1],  g_B1l[Nn0 * Nn1];
__device__ __nv_bfloat16 g_B1th[Nn1 * Nn0], g_B1tl[Nn1 * Nn0];
__device__ __nv_bfloat16 g_B2h[Nn1 * Nn2],  g_B2l[Nn1 * Nn2];
__device__ __nv_bfloat16 g_B2th[Nn2 * Nn1], g_B2tl[Nn2 * Nn1];

__device__ __nv_bfloat16 g_X0h[Nn0 * 6 * CC],  g_X0l[Nn0 * 6 * CC];
__device__ __nv_bfloat16 g_X1h[Nn1 * 12 * CC], g_X1l[Nn1 * 12 * CC];
__device__ __nv_bfloat16 g_X2h[Nn2 * 8 * CC],  g_X2l[Nn2 * 8 * CC];

// transposed bf16 buffers (distinct per concurrent chain)
__device__ __nv_bfloat16 g_bt0h[256 * Nn0],  g_bt0l[256 * Nn0];
__device__ __nv_bfloat16 g_bt1ah[256 * Nn1], g_bt1al[256 * Nn1];
__device__ __nv_bfloat16 g_bt1bh[256 * Nn1], g_bt1bl[256 * Nn1];
__device__ __nv_bfloat16 g_bt2h[256 * Nn2],  g_bt2l[256 * Nn2];
__device__ __nv_bfloat16 g_bt2bh[128 * Nn2], g_bt2bl[128 * Nn2];
__device__ __nv_bfloat16 g_bth0h[CC * Nn0],  g_bth0l[CC * Nn0];
__device__ __nv_bfloat16 g_bth1h[CC * Nn1],  g_bth1l[CC * Nn1];
__device__ __nv_bfloat16 g_bth2h[CC * Nn2],  g_bth2l[CC * Nn2];

__device__ __nv_bfloat16 g_W0h[CC * 6 * CC],  g_W0l[CC * 6 * CC];
__device__ __nv_bfloat16 g_W1h[CC * 12 * CC], g_W1l[CC * 12 * CC];
__device__ __nv_bfloat16 g_W2h[CC * 8 * CC],  g_W2l[CC * 8 * CC];

__constant__ int c_maps[3][12] = {
    {0, 3, 1, 4, 2, 5, -1, -1, -1, -1, -1, -1},
    {0, 5, -1, 8, 1, 6, 3, 9, 2, 7, 4, 10},
    {0, 5, 1, 6, 2, 7, 3, 4, -1, -1, -1, -1},
};

// ================= PTX helpers (plain sm_80+ PTX) =================
__device__ __forceinline__ uint32_t smem_u32(const void* p) {
    uint32_t a;
    asm("{ .reg .u64 t; cvta.to.shared.u64 t, %1; cvt.u32.u64 %0, t; }" : "=r"(a) : "l"(p));
    return a;
}
__device__ __forceinline__ void ldsm_x4(uint32_t* r, uint32_t a) {
    asm volatile("ldmatrix.sync.aligned.m8n8.x4.shared.b16 {%0,%1,%2,%3}, [%4];"
                 : "=r"(r[0]), "=r"(r[1]), "=r"(r[2]), "=r"(r[3]) : "r"(a));
}
__device__ __forceinline__ void mma_bf16(float* c, const uint32_t* a, const uint32_t* b) {
    asm volatile(
        "mma.sync.aligned.m16n8k16.row.col.f32.bf16.bf16.f32 "
        "{%0,%1,%2,%3}, {%4,%5,%6,%7}, {%8,%9}, {%0,%1,%2,%3};"
        : "+f"(c[0]), "+f"(c[1]), "+f"(c[2]), "+f"(c[3])
        : "r"(a[0]), "r"(a[1]), "r"(a[2]), "r"(a[3]), "r"(b[0]), "r"(b[1]));
}
__device__ __forceinline__ void cp_async16(uint32_t dst, const void* src, int sz) {
    asm volatile("cp.async.cg.shared.global [%0], [%1], 16, %2;"
                 :: "r"(dst), "l"(src), "r"(sz));
}
__device__ __forceinline__ uint32_t sw_addr(uint32_t tile_base, int r, int chunk) {
    return tile_base + (uint32_t)(r * 64) + (uint32_t)((chunk ^ ((r >> 1) & 3)) << 4);
}

// ================= batched bf16x3 HMMA GEMM =================
#define MM_SMEM (4 * 4 * 8192)
#define MAXJOB 6

struct MMJob {
    const __nv_bfloat16 *Ah, *Al, *Bh, *Bl;
    float* C;
    int M, K, lda, ldb, ldc, tileStart, tilesX;
};
struct MMParams { MMJob j[MAXJOB]; int n; };

__global__ __launch_bounds__(256)
void mmb_kernel(MMParams P)
{
    extern __shared__ __align__(128) char smem[];
    const uint32_t sbase = smem_u32(smem);
    const int tid = threadIdx.x, lane = tid & 31, wid = tid >> 5;
    const int wm = wid & 1, wn = wid >> 1;

    int bt = blockIdx.x;
    int ji = 0;
#pragma unroll 1
    while (ji + 1 < P.n && bt >= P.j[ji + 1].tileStart) ji++;
    const MMJob jb = P.j[ji];
    const int rel = bt - jb.tileStart;
    const int m0 = (rel % jb.tilesX) * 128;
    const int n0 = (rel / jb.tilesX) * 128;
    const int M = jb.M, K = jb.K, lda = jb.lda, ldb = jb.ldb, ldc = jb.ldc;
    const int mrows = (M - m0 < 128) ? (M - m0) : 128;
    const __nv_bfloat16* Ah = jb.Ah + (size_t)m0 * lda;
    const __nv_bfloat16* Al = jb.Al + (size_t)m0 * lda;
    const __nv_bfloat16* Bh = jb.Bh + (size_t)n0 * ldb;
    const __nv_bfloat16* Bl = jb.Bl + (size_t)n0 * ldb;
    float* C = jb.C;
    const int nk = (K + 31) >> 5;

    float acc[4][4][4];
#pragma unroll
    for (int i = 0; i < 4; i++)
#pragma unroll
        for (int j = 0; j < 4; j++)
#pragma unroll
            for (int v = 0; v < 4; v++) acc[i][j][v] = 0.f;

    auto load_stage = [&](int t) {
        const uint32_t sb = sbase + (uint32_t)(t & 3) * 32768;
        const int k0 = t << 5;
#pragma unroll
        for (int i = 0; i < 8; i++) {
            int idx = tid + i * 256;
            int tile = idx >> 9;
            int rem  = idx & 511;
            int r = rem >> 2, c = rem & 3;
            const __nv_bfloat16* gp;
            int ok;
            if (tile < 2) {
                gp = (tile == 0 ? Ah : Al) + (size_t)r * lda + k0 + c * 8;
                ok = (r < mrows) && (k0 + c * 8 < K);
            } else {
                gp = (tile == 2 ? Bh : Bl) + (size_t)r * ldb + k0 + c * 8;
                ok = (k0 + c * 8 < K);
            }
            cp_async16(sb + (uint32_t)tile * 8192 + sw_addr(0, r, c), gp, ok ? 16 : 0);
        }
    };

#pragma unroll
    for (int s = 0; s < 3; s++) {
        if (s < nk) load_stage(s);
        asm volatile("cp.async.commit_group;" ::: "memory");
    }

    const int frag_r = lane & 15;
    const int frag_c = lane >> 4;

    for (int t = 0; t < nk; t++) {
        asm volatile("cp.async.wait_group 2;" ::: "memory");
        __syncthreads();
        const uint32_t sb = sbase + (uint32_t)(t & 3) * 32768;
        const uint32_t tAh = sb, tAl = sb + 8192, tBh = sb + 16384, tBl = sb + 24576;

#pragma unroll
        for (int ks = 0; ks < 2; ks++) {
            const int ch = ks * 2 + frag_c;
            uint32_t ah[4][4], al[4][4], bh[4][2], bl[4][2];
#pragma unroll
            for (int mt = 0; mt < 4; mt++) {
                int r = wm * 64 + mt * 16 + frag_r;
                ldsm_x4(ah[mt], sw_addr(tAh, r, ch));
                ldsm_x4(al[mt], sw_addr(tAl, r, ch));
            }
#pragma unroll
            for (int j = 0; j < 2; j++) {
                int r = wn * 32 + j * 16 + frag_r;
                uint32_t rr[4];
                ldsm_x4(rr, sw_addr(tBh, r, ch));
                bh[2 * j][0] = rr[0]; bh[2 * j][1] = rr[2];
                bh[2 * j + 1][0] = rr[1]; bh[2 * j + 1][1] = rr[3];
                ldsm_x4(rr, sw_addr(tBl, r, ch));
                bl[2 * j][0] = rr[0]; bl[2 * j][1] = rr[2];
                bl[2 * j + 1][0] = rr[1]; bl[2 * j + 1][1] = rr[3];
            }
#pragma unroll
            for (int mt = 0; mt < 4; mt++)
#pragma unroll
                for (int nt = 0; nt < 4; nt++) {
                    mma_bf16(acc[mt][nt], ah[mt], bh[nt]);
                    mma_bf16(acc[mt][nt], ah[mt], bl[nt]);
                    mma_bf16(acc[mt][nt], al[mt], bh[nt]);
                }
        }
        if (t + 3 < nk) load_stage(t + 3);
        asm volatile("cp.async.commit_group;" ::: "memory");
    }

    const int er = lane >> 2, ec = (lane & 3) * 2;
#pragma unroll
    for (int mt = 0; mt < 4; mt++) {
        int row0 = m0 + wm * 64 + mt * 16 + er;
#pragma unroll
        for (int nt = 0; nt < 4; nt++) {
            int col = n0 + wn * 32 + nt * 8 + ec;
            if (row0 < M)
                *(float2*)&C[(size_t)row0 * ldc + col] = make_float2(acc[mt][nt][0], acc[mt][nt][1]);
            if (row0 + 8 < M)
                *(float2*)&C[(size_t)(row0 + 8) * ldc + col] = make_float2(acc[mt][nt][2], acc[mt][nt][3]);
        }
    }
}

// ================= batched split (elementwise, vectorized x4) =================
struct SJob { const float* src; __nv_bfloat16 *dh, *dl; int n4, blkStart; };
struct SParams { SJob j[8]; int n; };

__global__ void splitb_kernel(SParams P)
{
    int b = blockIdx.x;
    int ji = 0;
#pragma unroll 1
    while (ji + 1 < P.n && b >= P.j[ji + 1].blkStart) ji++;
    const SJob jb = P.j[ji];
    int i = (b - jb.blkStart) * 256 + threadIdx.x;
    if (i >= jb.n4) return;
    float4 v = ((const float4*)jb.src)[i];
    __nv_bfloat162 h0 = __floats2bfloat162_rn(v.x, v.y);
    __nv_bfloat162 h1 = __floats2bfloat162_rn(v.z, v.w);
    __nv_bfloat162 l0 = __floats2bfloat162_rn(v.x - __bfloat162float(h0.x),
                                              v.y - __bfloat162float(h0.y));
    __nv_bfloat162 l1 = __floats2bfloat162_rn(v.z - __bfloat162float(h1.x),
                                              v.w - __bfloat162float(h1.y));
    ((__nv_bfloat162*)jb.dh)[i * 2]     = h0;
    ((__nv_bfloat162*)jb.dh)[i * 2 + 1] = h1;
    ((__nv_bfloat162*)jb.dl)[i * 2]     = l0;
    ((__nv_bfloat162*)jb.dl)[i * 2 + 1] = l1;
}

// ================= batched transpose-split =================
// dst[n*rows + k] = src[k*lds + n] for k<rows, n<cols
struct TJob { const float* src; __nv_bfloat16 *dh, *dl; int lds, rows, cols, tileStart, tilesR; };
struct TParams { TJob j[6]; int n; };

__global__ void tsplitb_kernel(TParams P)
{
    __shared__ float tile[32][33];
    int b = blockIdx.x;
    int ji = 0;
#pragma unroll 1
    while (ji + 1 < P.n && b >= P.j[ji + 1].tileStart) ji++;
    const TJob jb = P.j[ji];
    int rel = b - jb.tileStart;
    int k0 = (rel % jb.tilesR) * 32, n0 = (rel / jb.tilesR) * 32;
    int tx = threadIdx.x, ty = threadIdx.y;
    for (int i = ty; i < 32; i += 8) {
        int k = k0 + i, n = n0 + tx;
        tile[i][tx] = (k < jb.rows && n < jb.cols) ? jb.src[(size_t)k * jb.lds + n] : 0.f;
    }
    __syncthreads();
    for (int i = ty; i < 32; i += 8) {
        int n = n0 + i, k = k0 + tx;
        if (n < jb.cols && k < jb.rows) {
            float v = tile[tx][i];
            __nv_bfloat16 h = __float2bfloat16(v);
            jb.dh[(size_t)n * jb.rows + k] = h;
            jb.dl[(size_t)n * jb.rows + k] = __float2bfloat16(v - __bfloat162float(h));
        }
    }
}

// ================= batched row copy (width 128) =================
struct CJob { const float* src; float* dst; int rows, ldd, rowStart; };
struct CParams { CJob j[6]; int n; };

__global__ void copyb_kernel(CParams P)
{
    int b = blockIdx.x;
    int ji = 0;
#pragma unroll 1
    while (ji + 1 < P.n && b >= P.j[ji + 1].rowStart) ji++;
    const CJob jb = P.j[ji];
    int r = b - jb.rowStart;
    jb.dst[(size_t)r * jb.ldd + threadIdx.x] = jb.src[(size_t)r * CC + threadIdx.x];
}

// ================= batched input linear =================
struct LJob { const float *x, *W, *b; float* y; int rows, rowStart; };
struct LParams { LJob j[3]; int n; };

__global__ void linb_kernel(LParams P)
{
    __shared__ float xs[CC];
    int b = blockIdx.x;
    int ji = 0;
#pragma unroll 1
    while (ji + 1 < P.n && b >= P.j[ji + 1].rowStart) ji++;
    const LJob jb = P.j[ji];
    int n = b - jb.rowStart, o = threadIdx.x;
    xs[o] = jb.x[(size_t)n * CC + o];
    __syncthreads();
    float acc = jb.b[o];
    const float* wr = &jb.W[(size_t)o * CC];
#pragma unroll 8
    for (int i = 0; i < CC; i++) acc += xs[i] * wr[i];
    jb.y[(size_t)n * CC + o] = acc;
}

// ================= misc small kernels =================
__global__ void build_wt_kernel(const float* __restrict__ w,
                                __nv_bfloat16* __restrict__ dh, __nv_bfloat16* __restrict__ dl,
                                int which, int korig, int S)
{
    int bi = blockIdx.x;
    int s = bi >> 7, o = bi & 127;
    int i = threadIdx.x;
    int k = c_maps[which][s];
    float v = (k >= 0) ? w[((size_t)i * CC + o) * korig + k] : 0.f;
    __nv_bfloat16 h = __float2bfloat16(v);
    size_t idx = (size_t)o * (S * CC) + s * CC + i;
    dh[idx] = h;
    dl[idx] = __float2bfloat16(v - __bfloat162float(h));
}

__global__ void head_kernel(const float* __restrict__ h0, const float* __restrict__ ow,
                            const float* __restrict__ ob, float* __restrict__ out, int total)
{
    int idx = blockIdx.x * blockDim.x + threadIdx.x;
    if (idx >= total) return;
    int n = idx >> 1, c = idx & 1;
    float acc = ob[c];
    const float* hr = &h0[(size_t)n * CC];
    const float* wr = &ow[(size_t)c * CC];
#pragma unroll 8
    for (int i = 0; i < CC; i++) acc += hr[i] * wr[i];
    out[idx] = 1.f / (1.f + expf(-acc));
}

// ================= host-side batch builders =================
struct MMBatch { MMParams p; int tiles; };
static void mmAdd(MMBatch& b,
                  const __nv_bfloat16* Ah, const __nv_bfloat16* Al, int lda,
                  const __nv_bfloat16* Bh, const __nv_bfloat16* Bl, int ldb,
                  float* C, int ldc, int M, int N, int K)
{
    MMJob& j = b.p.j[b.p.n++];
    j.Ah = Ah; j.Al = Al; j.Bh = Bh; j.Bl = Bl; j.C = C;
    j.M = M; j.K = K; j.lda = lda; j.ldb = ldb; j.ldc = ldc;
    j.tileStart = b.tiles; j.tilesX = (M + 127) / 128;
    b.tiles += j.tilesX * (N / 128);
}
static void mmRun(MMBatch& b)
{
    if (b.p.n) mmb_kernel<<<b.tiles, 256, MM_SMEM>>>(b.p);
    b.p.n = 0; b.tiles = 0;
}

struct SBatch { SParams p; int blks; };
static void sAdd(SBatch& b, const float* src, __nv_bfloat16* dh, __nv_bfloat16* dl, size_t cnt)
{
    SJob& j = b.p.j[b.p.n++];
    j.src = src; j.dh = dh; j.dl = dl; j.n4 = (int)(cnt / 4); j.blkStart = b.blks;
    b.blks += (j.n4 + 255) / 256;
}
static void sRun(SBatch& b)
{
    if (b.p.n) splitb_kernel<<<b.blks, 256>>>(b.p);
    b.p.n = 0; b.blks = 0;
}

struct TBatch { TParams p; int tiles; };
static void tAdd(TBatch& b, const float* src, int lds, int rows, int cols,
                 __nv_bfloat16* dh, __nv_bfloat16* dl)
{
    TJob& j = b.p.j[b.p.n++];
    j.src = src; j.dh = dh; j.dl = dl; j.lds = lds; j.rows = rows; j.cols = cols;
    j.tileStart = b.tiles; j.tilesR = (rows + 31) / 32;
    b.tiles += j.tilesR * ((cols + 31) / 32);
}
static void tRun(TBatch& b)
{
    if (b.p.n) tsplitb_kernel<<<b.tiles, dim3(32, 8)>>>(b.p);
    b.p.n = 0; b.tiles = 0;
}

#define SYM(v, g) { void* p_; cudaGetSymbolAddress(&p_, g); v = (decltype(v))p_; }

extern "C" void kernel_launch(void* const* d_in, const int* in_sizes, int n_in,
                              void* d_out, int out_size)
{
    (void)in_sizes; (void)n_in; (void)out_size;
    const float* x0    = (const float*)d_in[0];
    const float* x1    = (const float*)d_in[1];
    const float* x2    = (const float*)d_in[2];
    const float* L0    = (const float*)d_in[3];
    const float* L1d   = (const float*)d_in[4];
    const float* L1u   = (const float*)d_in[5];
    const float* L2d   = (const float*)d_in[6];
    const float* L2u   = (const float*)d_in[7];
    const float* B1    = (const float*)d_in[8];
    const float* B2    = (const float*)d_in[9];
    const float* in_w0 = (const float*)d_in[10];
    const float* in_b0 = (const float*)d_in[11];
    const float* in_w1 = (const float*)d_in[12];
    const float* in_b1 = (const float*)d_in[13];
    const float* in_w2 = (const float*)d_in[14];
    const float* in_b2 = (const float*)d_in[15];
    const float* lw[2][3] = {
        {(const float*)d_in[16], (const float*)d_in[17], (const float*)d_in[18]},
        {(const float*)d_in[19], (const float*)d_in[20], (const float*)d_in[21]},
    };
    const float* out_w = (const float*)d_in[22];
    const float* out_b = (const float*)d_in[23];
    float* out = (float*)d_out;

    cudaFuncSetAttribute(mmb_kernel, cudaFuncAttributeMaxDynamicSharedMemorySize, MM_SMEM);

    float *h0, *h1, *h2, *X0f, *X1f, *X2f;
    SYM(h0, g_h0); SYM(h1, g_h1); SYM(h2, g_h2);
    SYM(X0f, g_X0f); SYM(X1f, g_X1f); SYM(X2f, g_X2f);
    __nv_bfloat16 *L0h, *L0l, *L1dh, *L1dl, *L1uh, *L1ul, *L2dh, *L2dl, *L2uh, *L2ul;
    __nv_bfloat16 *B1h, *B1l, *B1th, *B1tl, *B2h, *B2l, *B2th, *B2tl;
    SYM(L0h, g_L0h); SYM(L0l, g_L0l);
    SYM(L1dh, g_L1dh); SYM(L1dl, g_L1dl); SYM(L1uh, g_L1uh); SYM(L1ul, g_L1ul);
    SYM(L2dh, g_L2dh); SYM(L2dl, g_L2dl); SYM(L2uh, g_L2uh); SYM(L2ul, g_L2ul);
    SYM(B1h, g_B1h); SYM(B1l, g_B1l); SYM(B1th, g_B1th); SYM(B1tl, g_B1tl);
    SYM(B2h, g_B2h); SYM(B2l, g_B2l); SYM(B2th, g_B2th); SYM(B2tl, g_B2tl);
    __nv_bfloat16 *X0h, *X0l, *X1h, *X1l, *X2h, *X2l;
    SYM(X0h, g_X0h); SYM(X0l, g_X0l); SYM(X1h, g_X1h); SYM(X1l, g_X1l);
    SYM(X2h, g_X2h); SYM(X2l, g_X2l);
    __nv_bfloat16 *bt0h, *bt0l, *bt1ah, *bt1al, *bt1bh, *bt1bl, *bt2h, *bt2l, *bt2bh, *bt2bl;
    SYM(bt0h, g_bt0h); SYM(bt0l, g_bt0l);
    SYM(bt1ah, g_bt1ah); SYM(bt1al, g_bt1al);
    SYM(bt1bh, g_bt1bh); SYM(bt1bl, g_bt1bl);
    SYM(bt2h, g_bt2h); SYM(bt2l, g_bt2l);
    SYM(bt2bh, g_bt2bh); SYM(bt2bl, g_bt2bl);
    __nv_bfloat16 *bh0h, *bh0l, *bh1h, *bh1l, *bh2h, *bh2l;
    SYM(bh0h, g_bth0h); SYM(bh0l, g_bth0l);
    SYM(bh1h, g_bth1h); SYM(bh1l, g_bth1l);
    SYM(bh2h, g_bth2h); SYM(bh2l, g_bth2l);
    __nv_bfloat16 *W0h, *W0l, *W1h, *W1l, *W2h, *W2l;
    SYM(W0h, g_W0h); SYM(W0l, g_W0l); SYM(W1h, g_W1h); SYM(W1l, g_W1l);
    SYM(W2h, g_W2h); SYM(W2l, g_W2l);

    const int LD0 = 6 * CC, LD1 = 12 * CC, LD2 = 8 * CC;

    MMBatch mb = {}; SBatch sb = {}; TBatch tb = {};

    // ---- operator splits (one launch) ----
    sAdd(sb, L0,  L0h,  L0l,  (size_t)Nn0 * Nn0);
    sAdd(sb, L1d, L1dh, L1dl, (size_t)Nn1 * Nn1);
    sAdd(sb, L1u, L1uh, L1ul, (size_t)Nn1 * Nn1);
    sAdd(sb, L2d, L2dh, L2dl, (size_t)Nn2 * Nn2);
    sAdd(sb, L2u, L2uh, L2ul, (size_t)Nn2 * Nn2);
    sAdd(sb, B1,  B1h,  B1l,  (size_t)Nn0 * Nn1);
    sAdd(sb, B2,  B2h,  B2l,  (size_t)Nn1 * Nn2);
    sRun(sb);
    tAdd(tb, B1, Nn1, Nn0, Nn1, B1th, B1tl);
    tAdd(tb, B2, Nn2, Nn1, Nn2, B2th, B2tl);
    tRun(tb);

    // ---- input linears (one launch) ----
    {
        LParams lp = {};
        lp.j[0] = { x0, in_w0, in_b0, h0, Nn0, 0 };
        lp.j[1] = { x1, in_w1, in_b1, h1, Nn1, Nn0 };
        lp.j[2] = { x2, in_w2, in_b2, h2, Nn2, Nn0 + Nn1 };
        lp.n = 3;
        linb_kernel<<<Nn0 + Nn1 + Nn2, CC>>>(lp);
    }

    for (int layer = 0; layer < 2; layer++) {
        build_wt_kernel<<<6 * CC,  CC>>>(lw[layer][0], W0h, W0l, 0, 6,  6);
        build_wt_kernel<<<12 * CC, CC>>>(lw[layer][1], W1h, W1l, 1, 11, 12);
        build_wt_kernel<<<8 * CC,  CC>>>(lw[layer][2], W2h, W2l, 2, 8,  8);

        // h transposes (one launch)
        tAdd(tb, h0, CC, Nn0, CC, bh0h, bh0l);
        tAdd(tb, h1, CC, Nn1, CC, bh1h, bh1l);
        tAdd(tb, h2, CC, Nn2, CC, bh2h, bh2l);
        tRun(tb);

        // base copies (one launch)
        {
            CParams cp = {};
            cp.j[0] = { h0, X0f + 0,   Nn0, LD0, 0 };
            cp.j[1] = { h1, X1f + 0,   Nn1, LD1, Nn0 };
            cp.j[2] = { h1, X1f + 256, Nn1, LD1, Nn0 + Nn1 };
            cp.j[3] = { h2, X2f + 0,   Nn2, LD2, Nn0 + 2 * Nn1 };
            cp.n = 4;
            copyb_kernel<<<Nn0 + 2 * Nn1 + Nn2, CC>>>(cp);
        }

        // projections (one batched GEMM launch, 142 CTAs)
        mmAdd(mb, B1h,  B1l,  Nn1, bh1h, bh1l, Nn1, X0f + 128, LD0, Nn0, 128, Nn1);
        mmAdd(mb, B1th, B1tl, Nn0, bh0h, bh0l, Nn0, X1f + 128, LD1, Nn1, 128, Nn0);
        mmAdd(mb, B2h,  B2l,  Nn2, bh2h, bh2l, Nn2, X1f + 384, LD1, Nn1, 128, Nn2);
        mmAdd(mb, B2th, B2tl, Nn1, bh1h, bh1l, Nn1, X2f + 128, LD2, Nn2, 128, Nn1);
        mmRun(mb);

        // first-hop transposes (one launch)
        tAdd(tb, X0f + 0,   LD0, Nn0, 256, bt0h,  bt0l);
        tAdd(tb, X1f + 0,   LD1, Nn1, 256, bt1ah, bt1al);
        tAdd(tb, X1f + 256, LD1, Nn1, 256, bt1bh, bt1bl);
        tAdd(tb, X2f + 0,   LD2, Nn2, 256, bt2h,  bt2l);
        tRun(tb);

        // first hops (one batched GEMM launch, 316 CTAs)
        mmAdd(mb, L0h,  L0l,  Nn0, bt0h,  bt0l,  Nn0, X0f + 256, LD0, Nn0, 256, Nn0);
        mmAdd(mb, L1dh, L1dl, Nn1, bt1ah, bt1al, Nn1, X1f + 512, LD1, Nn1, 256, Nn1);
        mmAdd(mb, L1uh, L1ul, Nn1, bt1bh, bt1bl, Nn1, X1f + 768, LD1, Nn1, 256, Nn1);
        mmAdd(mb, L2dh, L2dl, Nn2, bt2h,  bt2l,  Nn2, X2f + 256, LD2, Nn2, 256, Nn2);
        mmAdd(mb, L2uh, L2ul, Nn2, bh2h,  bh2l,  Nn2, X2f + 768, LD2, Nn2, 128, Nn2);
        mmRun(mb);

        // second-hop transposes (one launch)
        tAdd(tb, X0f + 256, LD0, Nn0, 256, bt0h,  bt0l);
        tAdd(tb, X1f + 512, LD1, Nn1, 256, bt1ah, bt1al);
        tAdd(tb, X1f + 768, LD1, Nn1, 256, bt1bh, bt1bl);
        tAdd(tb, X2f + 256, LD2, Nn2, 256, bt2h,  bt2l);
        tAdd(tb, X2f + 768, LD2, Nn2, 128, bt2bh, bt2bl);
        tRun(tb);

        // second hops (one batched GEMM launch, 316 CTAs)
        mmAdd(mb, L0h,  L0l,  Nn0, bt0h,  bt0l,  Nn0, X0f + 512,  LD0, Nn0, 256, Nn0);
        mmAdd(mb, L1dh, L1dl, Nn1, bt1ah, bt1al, Nn1, X1f + 1024, LD1, Nn1, 256, Nn1);
        mmAdd(mb, L1uh, L1ul, Nn1, bt1bh, bt1bl, Nn1, X1f + 1280, LD1, Nn1, 256, Nn1);
        mmAdd(mb, L2dh, L2dl, Nn2, bt2h,  bt2l,  Nn2, X2f + 512,  LD2, Nn2, 256, Nn2);
        mmAdd(mb, L2uh, L2ul, Nn2, bt2bh, bt2bl, Nn2, X2f + 896,  LD2, Nn2, 128, Nn2);
        mmRun(mb);

        // einsum A splits (one launch)
        sAdd(sb, X0f, X0h, X0l, (size_t)Nn0 * LD0);
        sAdd(sb, X1f, X1h, X1l, (size_t)Nn1 * LD1);
        sAdd(sb, X2f, X2h, X2l, (size_t)Nn2 * LD2);
        sRun(sb);

        // einsums (one batched GEMM launch)
        mmAdd(mb, X0h, X0l, LD0, W0h, W0l, LD0, h0, CC, Nn0, 128, LD0);
        mmAdd(mb, X1h, X1l, LD1, W1h, W1l, LD1, h1, CC, Nn1, 128, LD1);
        mmAdd(mb, X2h, X2l, LD2, W2h, W2l, LD2, h2, CC, Nn2, 128, LD2);
        mmRun(mb);
    }

    head_kernel<<<(Nn0 * 2 + 255) / 256, 256>>>(h0, out_w, out_b, out, Nn0 * 2);
}

// round 6
// speedup vs baseline: 4.9011x; 1.0438x over previous
#include <cuda_runtime.h>
#include <cuda_bf16.h>
#include <math.h>
#include <stdint.h>

#define Nn0 2000
#define Nn1 6000
#define Nn2 4000
#define CC  128

// ================= static scratch (no allocation) =================
__device__ float g_h0[Nn0 * CC];
__device__ float g_h1[Nn1 * CC];
__device__ float g_h2[Nn2 * CC];
__device__ float g_X0f[Nn0 * 6  * CC];
__device__ float g_X1f[Nn1 * 12 * CC];
__device__ float g_X2f[Nn2 * 8  * CC];

__device__ __nv_bfloat16 g_L0h[Nn0 * Nn0],  g_L0l[Nn0 * Nn0];
__device__ __nv_bfloat16 g_L1dh[Nn1 * Nn1], g_L1dl[Nn1 * Nn1];
__device__ __nv_bfloat16 g_L1uh[Nn1 * Nn1], g_L1ul[Nn1 * Nn1];
__device__ __nv_bfloat16 g_L2dh[Nn2 * Nn2], g_L2dl[Nn2 * Nn2];
__device__ __nv_bfloat16 g_L2uh[Nn2 * Nn2], g_L2ul[Nn2 * Nn2];
__device__ __nv_bfloat16 g_B1h[Nn0 * Nn1],  g_B1l[Nn0 * Nn1];
__device__ __nv_bfloat16 g_B1th[Nn1 * Nn0], g_B1tl[Nn1 * Nn0];
__device__ __nv_bfloat16 g_B2h[Nn1 * Nn2],  g_B2l[Nn1 * Nn2];
__device__ __nv_bfloat16 g_B2th[Nn2 * Nn1], g_B2tl[Nn2 * Nn1];

__device__ __nv_bfloat16 g_X0h[Nn0 * 6 * CC],  g_X0l[Nn0 * 6 * CC];
__device__ __nv_bfloat16 g_X1h[Nn1 * 12 * CC], g_X1l[Nn1 * 12 * CC];
__device__ __nv_bfloat16 g_X2h[Nn2 * 8 * CC],  g_X2l[Nn2 * 8 * CC];

__device__ __nv_bfloat16 g_bt0h[256 * Nn0],  g_bt0l[256 * Nn0];
__device__ __nv_bfloat16 g_bt1ah[256 * Nn1], g_bt1al[256 * Nn1];
__device__ __nv_bfloat16 g_bt1bh[256 * Nn1], g_bt1bl[256 * Nn1];
__device__ __nv_bfloat16 g_bt2h[256 * Nn2],  g_bt2l[256 * Nn2];
__device__ __nv_bfloat16 g_bt2bh[128 * Nn2], g_bt2bl[128 * Nn2];
__device__ __nv_bfloat16 g_bth0h[CC * Nn0],  g_bth0l[CC * Nn0];
__device__ __nv_bfloat16 g_bth1h[CC * Nn1],  g_bth1l[CC * Nn1];
__device__ __nv_bfloat16 g_bth2h[CC * Nn2],  g_bth2l[CC * Nn2];

__device__ __nv_bfloat16 g_W0h[CC * 6 * CC],  g_W0l[CC * 6 * CC];
__device__ __nv_bfloat16 g_W1h[CC * 12 * CC], g_W1l[CC * 12 * CC];
__device__ __nv_bfloat16 g_W2h[CC * 8 * CC],  g_W2l[CC * 8 * CC];

__constant__ int c_maps[3][12] = {
    {0, 3, 1, 4, 2, 5, -1, -1, -1, -1, -1, -1},
    {0, 5, -1, 8, 1, 6, 3, 9, 2, 7, 4, 10},
    {0, 5, 1, 6, 2, 7, 3, 4, -1, -1, -1, -1},
};

// ================= PTX helpers (plain sm_80+ PTX) =================
__device__ __forceinline__ uint32_t smem_u32(const void* p) {
    uint32_t a;
    asm("{ .reg .u64 t; cvta.to.shared.u64 t, %1; cvt.u32.u64 %0, t; }" : "=r"(a) : "l"(p));
    return a;
}
__device__ __forceinline__ void ldsm_x4(uint32_t* r, uint32_t a) {
    asm volatile("ldmatrix.sync.aligned.m8n8.x4.shared.b16 {%0,%1,%2,%3}, [%4];"
                 : "=r"(r[0]), "=r"(r[1]), "=r"(r[2]), "=r"(r[3]) : "r"(a));
}
__device__ __forceinline__ void mma_bf16(float* c, const uint32_t* a, const uint32_t* b) {
    asm volatile(
        "mma.sync.aligned.m16n8k16.row.col.f32.bf16.bf16.f32 "
        "{%0,%1,%2,%3}, {%4,%5,%6,%7}, {%8,%9}, {%0,%1,%2,%3};"
        : "+f"(c[0]), "+f"(c[1]), "+f"(c[2]), "+f"(c[3])
        : "r"(a[0]), "r"(a[1]), "r"(a[2]), "r"(a[3]), "r"(b[0]), "r"(b[1]));
}
__device__ __forceinline__ void cp_async16(uint32_t dst, const void* src, int sz) {
    asm volatile("cp.async.cg.shared.global [%0], [%1], 16, %2;"
                 :: "r"(dst), "l"(src), "r"(sz));
}
__device__ __forceinline__ uint32_t sw_addr(uint32_t tile_base, int r, int chunk) {
    return tile_base + (uint32_t)(r * 64) + (uint32_t)((chunk ^ ((r >> 1) & 3)) << 4);
}

// ================= batched bf16x3 HMMA GEMM =================
// 3-stage pipeline, 96KB smem, 2 CTAs/SM target.
#define MM_SMEM (3 * 4 * 8192)
#define MAXJOB 6

struct MMJob {
    const __nv_bfloat16 *Ah, *Al, *Bh, *Bl;
    float* C;
    int M, K, lda, ldb, ldc, tileStart, tilesX;
};
struct MMParams { MMJob j[MAXJOB]; int n; };

__global__ __launch_bounds__(256, 2)
void mmb_kernel(MMParams P)
{
    extern __shared__ __align__(128) char smem[];
    const uint32_t sbase = smem_u32(smem);
    const int tid = threadIdx.x, lane = tid & 31, wid = tid >> 5;
    const int wm = wid & 1, wn = wid >> 1;

    int bt = blockIdx.x;
    int ji = 0;
#pragma unroll 1
    while (ji + 1 < P.n && bt >= P.j[ji + 1].tileStart) ji++;
    const MMJob jb = P.j[ji];
    const int rel = bt - jb.tileStart;
    const int m0 = (rel % jb.tilesX) * 128;
    const int n0 = (rel / jb.tilesX) * 128;
    const int M = jb.M, K = jb.K, lda = jb.lda, ldb = jb.ldb, ldc = jb.ldc;
    const int mrows = (M - m0 < 128) ? (M - m0) : 128;
    const __nv_bfloat16* Ah = jb.Ah + (size_t)m0 * lda;
    const __nv_bfloat16* Al = jb.Al + (size_t)m0 * lda;
    const __nv_bfloat16* Bh = jb.Bh + (size_t)n0 * ldb;
    const __nv_bfloat16* Bl = jb.Bl + (size_t)n0 * ldb;
    float* C = jb.C;
    const int nk = (K + 31) >> 5;

    float acc[4][4][4];
#pragma unroll
    for (int i = 0; i < 4; i++)
#pragma unroll
        for (int j = 0; j < 4; j++)
#pragma unroll
            for (int v = 0; v < 4; v++) acc[i][j][v] = 0.f;

    auto load_stage = [&](int t) {
        const uint32_t sb = sbase + (uint32_t)(t % 3) * 32768;
        const int k0 = t << 5;
#pragma unroll
        for (int i = 0; i < 8; i++) {
            int idx = tid + i * 256;
            int tile = idx >> 9;
            int rem  = idx & 511;
            int r = rem >> 2, c = rem & 3;
            const __nv_bfloat16* gp;
            int ok;
            if (tile < 2) {
                gp = (tile == 0 ? Ah : Al) + (size_t)r * lda + k0 + c * 8;
                ok = (r < mrows) && (k0 + c * 8 < K);
            } else {
                gp = (tile == 2 ? Bh : Bl) + (size_t)r * ldb + k0 + c * 8;
                ok = (k0 + c * 8 < K);
            }
            cp_async16(sb + (uint32_t)tile * 8192 + sw_addr(0, r, c), gp, ok ? 16 : 0);
        }
    };

    // prologue: 2 stages in flight
#pragma unroll
    for (int s = 0; s < 2; s++) {
        if (s < nk) load_stage(s);
        asm volatile("cp.async.commit_group;" ::: "memory");
    }

    const int frag_r = lane & 15;
    const int frag_c = lane >> 4;

    for (int t = 0; t < nk; t++) {
        asm volatile("cp.async.wait_group 1;" ::: "memory");
        __syncthreads();
        const uint32_t sb = sbase + (uint32_t)(t % 3) * 32768;
        const uint32_t tAh = sb, tAl = sb + 8192, tBh = sb + 16384, tBl = sb + 24576;

#pragma unroll
        for (int ks = 0; ks < 2; ks++) {
            const int ch = ks * 2 + frag_c;
            uint32_t bh[4][2], bl[4][2];
#pragma unroll
            for (int j = 0; j < 2; j++) {
                int r = wn * 32 + j * 16 + frag_r;
                uint32_t rr[4];
                ldsm_x4(rr, sw_addr(tBh, r, ch));
                bh[2 * j][0] = rr[0]; bh[2 * j][1] = rr[2];
                bh[2 * j + 1][0] = rr[1]; bh[2 * j + 1][1] = rr[3];
                ldsm_x4(rr, sw_addr(tBl, r, ch));
                bl[2 * j][0] = rr[0]; bl[2 * j][1] = rr[2];
                bl[2 * j + 1][0] = rr[1]; bl[2 * j + 1][1] = rr[3];
            }
#pragma unroll
            for (int mt = 0; mt < 4; mt++) {
                int r = wm * 64 + mt * 16 + frag_r;
                uint32_t ah[4], al[4];
                ldsm_x4(ah, sw_addr(tAh, r, ch));
                ldsm_x4(al, sw_addr(tAl, r, ch));
#pragma unroll
                for (int nt = 0; nt < 4; nt++) {
                    mma_bf16(acc[mt][nt], ah, bh[nt]);
                    mma_bf16(acc[mt][nt], ah, bl[nt]);
                    mma_bf16(acc[mt][nt], al, bh[nt]);
                }
            }
        }
        __syncthreads();
        if (t + 2 < nk) load_stage(t + 2);
        asm volatile("cp.async.commit_group;" ::: "memory");
    }

    const int er = lane >> 2, ec = (lane & 3) * 2;
#pragma unroll
    for (int mt = 0; mt < 4; mt++) {
        int row0 = m0 + wm * 64 + mt * 16 + er;
#pragma unroll
        for (int nt = 0; nt < 4; nt++) {
            int col = n0 + wn * 32 + nt * 8 + ec;
            if (row0 < M)
                *(float2*)&C[(size_t)row0 * ldc + col] = make_float2(acc[mt][nt][0], acc[mt][nt][1]);
            if (row0 + 8 < M)
                *(float2*)&C[(size_t)(row0 + 8) * ldc + col] = make_float2(acc[mt][nt][2], acc[mt][nt][3]);
        }
    }
}

// ================= batched split (8 floats/thread, 16B stores) =================
struct SJob { const float* src; __nv_bfloat16 *dh, *dl; int n8, blkStart; };
struct SParams { SJob j[8]; int n; };

__global__ void splitb_kernel(SParams P)
{
    int b = blockIdx.x;
    int ji = 0;
#pragma unroll 1
    while (ji + 1 < P.n && b >= P.j[ji + 1].blkStart) ji++;
    const SJob jb = P.j[ji];
    int i = (b - jb.blkStart) * 256 + threadIdx.x;
    if (i >= jb.n8) return;
    float4 v0 = ((const float4*)jb.src)[i * 2];
    float4 v1 = ((const float4*)jb.src)[i * 2 + 1];
    __nv_bfloat162 h[4], l[4];
    h[0] = __floats2bfloat162_rn(v0.x, v0.y);
    h[1] = __floats2bfloat162_rn(v0.z, v0.w);
    h[2] = __floats2bfloat162_rn(v1.x, v1.y);
    h[3] = __floats2bfloat162_rn(v1.z, v1.w);
    l[0] = __floats2bfloat162_rn(v0.x - __bfloat162float(h[0].x), v0.y - __bfloat162float(h[0].y));
    l[1] = __floats2bfloat162_rn(v0.z - __bfloat162float(h[1].x), v0.w - __bfloat162float(h[1].y));
    l[2] = __floats2bfloat162_rn(v1.x - __bfloat162float(h[2].x), v1.y - __bfloat162float(h[2].y));
    l[3] = __floats2bfloat162_rn(v1.z - __bfloat162float(h[3].x), v1.w - __bfloat162float(h[3].y));
    ((uint4*)jb.dh)[i] = *(uint4*)h;
    ((uint4*)jb.dl)[i] = *(uint4*)l;
}

// ================= batched transpose-split =================
struct TJob { const float* src; __nv_bfloat16 *dh, *dl; int lds, rows, cols, tileStart, tilesR; };
struct TParams { TJob j[6]; int n; };

__global__ void tsplitb_kernel(TParams P)
{
    __shared__ float tile[32][33];
    int b = blockIdx.x;
    int ji = 0;
#pragma unroll 1
    while (ji + 1 < P.n && b >= P.j[ji + 1].tileStart) ji++;
    const TJob jb = P.j[ji];
    int rel = b - jb.tileStart;
    int k0 = (rel % jb.tilesR) * 32, n0 = (rel / jb.tilesR) * 32;
    int tx = threadIdx.x, ty = threadIdx.y;
    for (int i = ty; i < 32; i += 8) {
        int k = k0 + i, n = n0 + tx;
        tile[i][tx] = (k < jb.rows && n < jb.cols) ? jb.src[(size_t)k * jb.lds + n] : 0.f;
    }
    __syncthreads();
    for (int i = ty; i < 32; i += 8) {
        int n = n0 + i, k = k0 + tx;
        if (n < jb.cols && k < jb.rows) {
            float v = tile[tx][i];
            __nv_bfloat16 h = __float2bfloat16(v);
            jb.dh[(size_t)n * jb.rows + k] = h;
            jb.dl[(size_t)n * jb.rows + k] = __float2bfloat16(v - __bfloat162float(h));
        }
    }
}

// ================= batched row copy (width 128) =================
struct CJob { const float* src; float* dst; int rows, ldd, rowStart; };
struct CParams { CJob j[6]; int n; };

__global__ void copyb_kernel(CParams P)
{
    int b = blockIdx.x;
    int ji = 0;
#pragma unroll 1
    while (ji + 1 < P.n && b >= P.j[ji + 1].rowStart) ji++;
    const CJob jb = P.j[ji];
    int r = b - jb.rowStart;
    jb.dst[(size_t)r * jb.ldd + threadIdx.x] = jb.src[(size_t)r * CC + threadIdx.x];
}

// ================= batched input linear =================
struct LJob { const float *x, *W, *b; float* y; int rows, rowStart; };
struct LParams { LJob j[3]; int n; };

__global__ void linb_kernel(LParams P)
{
    __shared__ float xs[CC];
    int b = blockIdx.x;
    int ji = 0;
#pragma unroll 1
    while (ji + 1 < P.n && b >= P.j[ji + 1].rowStart) ji++;
    const LJob jb = P.j[ji];
    int n = b - jb.rowStart, o = threadIdx.x;
    xs[o] = jb.x[(size_t)n * CC + o];
    __syncthreads();
    float acc = jb.b[o];
    const float* wr = &jb.W[(size_t)o * CC];
#pragma unroll 8
    for (int i = 0; i < CC; i++) acc += xs[i] * wr[i];
    jb.y[(size_t)n * CC + o] = acc;
}

// ================= misc small kernels =================
__global__ void build_wt_kernel(const float* __restrict__ w,
                                __nv_bfloat16* __restrict__ dh, __nv_bfloat16* __restrict__ dl,
                                int which, int korig, int S)
{
    int bi = blockIdx.x;
    int s = bi >> 7, o = bi & 127;
    int i = threadIdx.x;
    int k = c_maps[which][s];
    float v = (k >= 0) ? w[((size_t)i * CC + o) * korig + k] : 0.f;
    __nv_bfloat16 h = __float2bfloat16(v);
    size_t idx = (size_t)o * (S * CC) + s * CC + i;
    dh[idx] = h;
    dl[idx] = __float2bfloat16(v - __bfloat162float(h));
}

__global__ void head_kernel(const float* __restrict__ h0, const float* __restrict__ ow,
                            const float* __restrict__ ob, float* __restrict__ out, int total)
{
    int idx = blockIdx.x * blockDim.x + threadIdx.x;
    if (idx >= total) return;
    int n = idx >> 1, c = idx & 1;
    float acc = ob[c];
    const float* hr = &h0[(size_t)n * CC];
    const float* wr = &ow[(size_t)c * CC];
#pragma unroll 8
    for (int i = 0; i < CC; i++) acc += hr[i] * wr[i];
    out[idx] = 1.f / (1.f + expf(-acc));
}

// ================= host-side batch builders =================
struct MMBatch { MMParams p; int tiles; };
static void mmAdd(MMBatch& b,
                  const __nv_bfloat16* Ah, const __nv_bfloat16* Al, int lda,
                  const __nv_bfloat16* Bh, const __nv_bfloat16* Bl, int ldb,
                  float* C, int ldc, int M, int N, int K)
{
    MMJob& j = b.p.j[b.p.n++];
    j.Ah = Ah; j.Al = Al; j.Bh = Bh; j.Bl = Bl; j.C = C;
    j.M = M; j.K = K; j.lda = lda; j.ldb = ldb; j.ldc = ldc;
    j.tileStart = b.tiles; j.tilesX = (M + 127) / 128;
    b.tiles += j.tilesX * (N / 128);
}
static void mmRun(MMBatch& b)
{
    if (b.p.n) mmb_kernel<<<b.tiles, 256, MM_SMEM>>>(b.p);
    b.p.n = 0; b.tiles = 0;
}

struct SBatch { SParams p; int blks; };
static void sAdd(SBatch& b, const float* src, __nv_bfloat16* dh, __nv_bfloat16* dl, size_t cnt)
{
    SJob& j = b.p.j[b.p.n++];
    j.src = src; j.dh = dh; j.dl = dl; j.n8 = (int)(cnt / 8); j.blkStart = b.blks;
    b.blks += (j.n8 + 255) / 256;
}
static void sRun(SBatch& b)
{
    if (b.p.n) splitb_kernel<<<b.blks, 256>>>(b.p);
    b.p.n = 0; b.blks = 0;
}

struct TBatch { TParams p; int tiles; };
static void tAdd(TBatch& b, const float* src, int lds, int rows, int cols,
                 __nv_bfloat16* dh, __nv_bfloat16* dl)
{
    TJob& j = b.p.j[b.p.n++];
    j.src = src; j.dh = dh; j.dl = dl; j.lds = lds; j.rows = rows; j.cols = cols;
    j.tileStart = b.tiles; j.tilesR = (rows + 31) / 32;
    b.tiles += j.tilesR * ((cols + 31) / 32);
}
static void tRun(TBatch& b)
{
    if (b.p.n) tsplitb_kernel<<<b.tiles, dim3(32, 8)>>>(b.p);
    b.p.n = 0; b.tiles = 0;
}

#define SYM(v, g) { void* p_; cudaGetSymbolAddress(&p_, g); v = (decltype(v))p_; }

extern "C" void kernel_launch(void* const* d_in, const int* in_sizes, int n_in,
                              void* d_out, int out_size)
{
    (void)in_sizes; (void)n_in; (void)out_size;
    const float* x0    = (const float*)d_in[0];
    const float* x1    = (const float*)d_in[1];
    const float* x2    = (const float*)d_in[2];
    const float* L0    = (const float*)d_in[3];
    const float* L1d   = (const float*)d_in[4];
    const float* L1u   = (const float*)d_in[5];
    const float* L2d   = (const float*)d_in[6];
    const float* L2u   = (const float*)d_in[7];
    const float* B1    = (const float*)d_in[8];
    const float* B2    = (const float*)d_in[9];
    const float* in_w0 = (const float*)d_in[10];
    const float* in_b0 = (const float*)d_in[11];
    const float* in_w1 = (const float*)d_in[12];
    const float* in_b1 = (const float*)d_in[13];
    const float* in_w2 = (const float*)d_in[14];
    const float* in_b2 = (const float*)d_in[15];
    const float* lw[2][3] = {
        {(const float*)d_in[16], (const float*)d_in[17], (const float*)d_in[18]},
        {(const float*)d_in[19], (const float*)d_in[20], (const float*)d_in[21]},
    };
    const float* out_w = (const float*)d_in[22];
    const float* out_b = (const float*)d_in[23];
    float* out = (float*)d_out;

    cudaFuncSetAttribute(mmb_kernel, cudaFuncAttributeMaxDynamicSharedMemorySize, MM_SMEM);

    float *h0, *h1, *h2, *X0f, *X1f, *X2f;
    SYM(h0, g_h0); SYM(h1, g_h1); SYM(h2, g_h2);
    SYM(X0f, g_X0f); SYM(X1f, g_X1f); SYM(X2f, g_X2f);
    __nv_bfloat16 *L0h, *L0l, *L1dh, *L1dl, *L1uh, *L1ul, *L2dh, *L2dl, *L2uh, *L2ul;
    __nv_bfloat16 *B1h, *B1l, *B1th, *B1tl, *B2h, *B2l, *B2th, *B2tl;
    SYM(L0h, g_L0h); SYM(L0l, g_L0l);
    SYM(L1dh, g_L1dh); SYM(L1dl, g_L1dl); SYM(L1uh, g_L1uh); SYM(L1ul, g_L1ul);
    SYM(L2dh, g_L2dh); SYM(L2dl, g_L2dl); SYM(L2uh, g_L2uh); SYM(L2ul, g_L2ul);
    SYM(B1h, g_B1h); SYM(B1l, g_B1l); SYM(B1th, g_B1th); SYM(B1tl, g_B1tl);
    SYM(B2h, g_B2h); SYM(B2l, g_B2l); SYM(B2th, g_B2th); SYM(B2tl, g_B2tl);
    __nv_bfloat16 *X0h, *X0l, *X1h, *X1l, *X2h, *X2l;
    SYM(X0h, g_X0h); SYM(X0l, g_X0l); SYM(X1h, g_X1h); SYM(X1l, g_X1l);
    SYM(X2h, g_X2h); SYM(X2l, g_X2l);
    __nv_bfloat16 *bt0h, *bt0l, *bt1ah, *bt1al, *bt1bh, *bt1bl, *bt2h, *bt2l, *bt2bh, *bt2bl;
    SYM(bt0h, g_bt0h); SYM(bt0l, g_bt0l);
    SYM(bt1ah, g_bt1ah); SYM(bt1al, g_bt1al);
    SYM(bt1bh, g_bt1bh); SYM(bt1bl, g_bt1bl);
    SYM(bt2h, g_bt2h); SYM(bt2l, g_bt2l);
    SYM(bt2bh, g_bt2bh); SYM(bt2bl, g_bt2bl);
    __nv_bfloat16 *bh0h, *bh0l, *bh1h, *bh1l, *bh2h, *bh2l;
    SYM(bh0h, g_bth0h); SYM(bh0l, g_bth0l);
    SYM(bh1h, g_bth1h); SYM(bh1l, g_bth1l);
    SYM(bh2h, g_bth2h); SYM(bh2l, g_bth2l);
    __nv_bfloat16 *W0h, *W0l, *W1h, *W1l, *W2h, *W2l;
    SYM(W0h, g_W0h); SYM(W0l, g_W0l); SYM(W1h, g_W1h); SYM(W1l, g_W1l);
    SYM(W2h, g_W2h); SYM(W2l, g_W2l);

    const int LD0 = 6 * CC, LD1 = 12 * CC, LD2 = 8 * CC;

    MMBatch mb = {}; SBatch sb = {}; TBatch tb = {};

    // ---- operator splits (one launch) ----
    sAdd(sb, L0,  L0h,  L0l,  (size_t)Nn0 * Nn0);
    sAdd(sb, L1d, L1dh, L1dl, (size_t)Nn1 * Nn1);
    sAdd(sb, L1u, L1uh, L1ul, (size_t)Nn1 * Nn1);
    sAdd(sb, L2d, L2dh, L2dl, (size_t)Nn2 * Nn2);
    sAdd(sb, L2u, L2uh, L2ul, (size_t)Nn2 * Nn2);
    sAdd(sb, B1,  B1h,  B1l,  (size_t)Nn0 * Nn1);
    sAdd(sb, B2,  B2h,  B2l,  (size_t)Nn1 * Nn2);
    sRun(sb);
    tAdd(tb, B1, Nn1, Nn0, Nn1, B1th, B1tl);
    tAdd(tb, B2, Nn2, Nn1, Nn2, B2th, B2tl);
    tRun(tb);

    // ---- input linears (one launch) ----
    {
        LParams lp = {};
        lp.j[0] = { x0, in_w0, in_b0, h0, Nn0, 0 };
        lp.j[1] = { x1, in_w1, in_b1, h1, Nn1, Nn0 };
        lp.j[2] = { x2, in_w2, in_b2, h2, Nn2, Nn0 + Nn1 };
        lp.n = 3;
        linb_kernel<<<Nn0 + Nn1 + Nn2, CC>>>(lp);
    }

    for (int layer = 0; layer < 2; layer++) {
        build_wt_kernel<<<6 * CC,  CC>>>(lw[layer][0], W0h, W0l, 0, 6,  6);
        build_wt_kernel<<<12 * CC, CC>>>(lw[layer][1], W1h, W1l, 1, 11, 12);
        build_wt_kernel<<<8 * CC,  CC>>>(lw[layer][2], W2h, W2l, 2, 8,  8);

        // h transposes (one launch)
        tAdd(tb, h0, CC, Nn0, CC, bh0h, bh0l);
        tAdd(tb, h1, CC, Nn1, CC, bh1h, bh1l);
        tAdd(tb, h2, CC, Nn2, CC, bh2h, bh2l);
        tRun(tb);

        // base copies (one launch)
        {
            CParams cp = {};
            cp.j[0] = { h0, X0f + 0,   Nn0, LD0, 0 };
            cp.j[1] = { h1, X1f + 0,   Nn1, LD1, Nn0 };
            cp.j[2] = { h1, X1f + 256, Nn1, LD1, Nn0 + Nn1 };
            cp.j[3] = { h2, X2f + 0,   Nn2, LD2, Nn0 + 2 * Nn1 };
            cp.n = 4;
            copyb_kernel<<<Nn0 + 2 * Nn1 + Nn2, CC>>>(cp);
        }

        // projections (one batched GEMM launch)
        mmAdd(mb, B1h,  B1l,  Nn1, bh1h, bh1l, Nn1, X0f + 128, LD0, Nn0, 128, Nn1);
        mmAdd(mb, B1th, B1tl, Nn0, bh0h, bh0l, Nn0, X1f + 128, LD1, Nn1, 128, Nn0);
        mmAdd(mb, B2h,  B2l,  Nn2, bh2h, bh2l, Nn2, X1f + 384, LD1, Nn1, 128, Nn2);
        mmAdd(mb, B2th, B2tl, Nn1, bh1h, bh1l, Nn1, X2f + 128, LD2, Nn2, 128, Nn1);
        mmRun(mb);

        // first-hop transposes (one launch)
        tAdd(tb, X0f + 0,   LD0, Nn0, 256, bt0h,  bt0l);
        tAdd(tb, X1f + 0,   LD1, Nn1, 256, bt1ah, bt1al);
        tAdd(tb, X1f + 256, LD1, Nn1, 256, bt1bh, bt1bl);
        tAdd(tb, X2f + 0,   LD2, Nn2, 256, bt2h,  bt2l);
        tRun(tb);

        // first hops (one batched GEMM launch)
        mmAdd(mb, L0h,  L0l,  Nn0, bt0h,  bt0l,  Nn0, X0f + 256, LD0, Nn0, 256, Nn0);
        mmAdd(mb, L1dh, L1dl, Nn1, bt1ah, bt1al, Nn1, X1f + 512, LD1, Nn1, 256, Nn1);
        mmAdd(mb, L1uh, L1ul, Nn1, bt1bh, bt1bl, Nn1, X1f + 768, LD1, Nn1, 256, Nn1);
        mmAdd(mb, L2dh, L2dl, Nn2, bt2h,  bt2l,  Nn2, X2f + 256, LD2, Nn2, 256, Nn2);
        mmAdd(mb, L2uh, L2ul, Nn2, bh2h,  bh2l,  Nn2, X2f + 768, LD2, Nn2, 128, Nn2);
        mmRun(mb);

        // second-hop transposes (one launch)
        tAdd(tb, X0f + 256, LD0, Nn0, 256, bt0h,  bt0l);
        tAdd(tb, X1f + 512, LD1, Nn1, 256, bt1ah, bt1al);
        tAdd(tb, X1f + 768, LD1, Nn1, 256, bt1bh, bt1bl);
        tAdd(tb, X2f + 256, LD2, Nn2, 256, bt2h,  bt2l);
        tAdd(tb, X2f + 768, LD2, Nn2, 128, bt2bh, bt2bl);
        tRun(tb);

        // second hops (one batched GEMM launch)
        mmAdd(mb, L0h,  L0l,  Nn0, bt0h,  bt0l,  Nn0, X0f + 512,  LD0, Nn0, 256, Nn0);
        mmAdd(mb, L1dh, L1dl, Nn1, bt1ah, bt1al, Nn1, X1f + 1024, LD1, Nn1, 256, Nn1);
        mmAdd(mb, L1uh, L1ul, Nn1, bt1bh, bt1bl, Nn1, X1f + 1280, LD1, Nn1, 256, Nn1);
        mmAdd(mb, L2dh, L2dl, Nn2, bt2h,  bt2l,  Nn2, X2f + 512,  LD2, Nn2, 256, Nn2);
        mmAdd(mb, L2uh, L2ul, Nn2, bt2bh, bt2bl, Nn2, X2f + 896,  LD2, Nn2, 128, Nn2);
        mmRun(mb);

        // einsum A splits (one launch)
        sAdd(sb, X0f, X0h, X0l, (size_t)Nn0 * LD0);
        sAdd(sb, X1f, X1h, X1l, (size_t)Nn1 * LD1);
        sAdd(sb, X2f, X2h, X2l, (size_t)Nn2 * LD2);
        sRun(sb);

        // einsums (one batched GEMM launch)
        mmAdd(mb, X0h, X0l, LD0, W0h, W0l, LD0, h0, CC, Nn0, 128, LD0);
        mmAdd(mb, X1h, X1l, LD1, W1h, W1l, LD1, h1, CC, Nn1, 128, LD1);
        mmAdd(mb, X2h, X2l, LD2, W2h, W2l, LD2, h2, CC, Nn2, 128, LD2);
        mmRun(mb);
    }

    head_kernel<<<(Nn0 * 2 + 255) / 256, 256>>>(h0, out_w, out_b, out, Nn0 * 2);
}